// round 5
// baseline (speedup 1.0000x reference)
#include <cuda_runtime.h>
#include <cstddef>

// B=16, N=512, T=24, F=64, BT=384
#define T_DIM 24
#define N_DIM 512
#define BT_DIM 384

// Scratch (device globals: allocation-free per harness rules)
static __device__ float g_EE[N_DIM * N_DIM];                       // 1 MB
static __device__ float g_S[(size_t)BT_DIM * N_DIM * N_DIM];       // 403 MB: exp(relu(s)-D)
static __device__ float g_VW[(size_t)BT_DIM * N_DIM * 128];        // 100 MB [XW|UW]
static __device__ float g_D[(size_t)BT_DIM * N_DIM];               // diag shift per row
static __device__ float g_RSP[(size_t)BT_DIM * 4 * N_DIM];         // row-sum partials

typedef unsigned long long u64;
__device__ __forceinline__ u64 pack2(float lo, float hi) {
    u64 r; asm("mov.b64 %0, {%1, %2};" : "=l"(r) : "f"(lo), "f"(hi)); return r;
}
__device__ __forceinline__ u64 ffma2(u64 a, u64 b, u64 c) {
    u64 d; asm("fma.rn.f32x2 %0, %1, %2, %3;" : "=l"(d) : "l"(a), "l"(b), "l"(c)); return d;
}
__device__ __forceinline__ float2 unpack2(u64 v) {
    float2 r; asm("mov.b64 {%0, %1}, %2;" : "=f"(r.x), "=f"(r.y) : "l"(v)); return r;
}

#define A2P 260  // k_logits As2 dup pitch (floats): 256 + 4, even
#define BP  130  // k-major (k,c) pitch, even for LDS.64
#define AP  68   // k_out Ps row-major pitch
#define VP  132  // k_out Vs pitch
#define WP  66   // k_vw Ws pitch

// ---------------------------------------------------------------------------
// k_ee: EE = emb @ emb^T  (512x512, K=64)
// ---------------------------------------------------------------------------
__global__ void k_ee(const float* __restrict__ emb) {
    __shared__ float As[64][68];
    __shared__ float Bs[64][65];
    const int rb = blockIdx.y * 64, cb = blockIdx.x * 64;
    const int tid = threadIdx.x;
    #pragma unroll
    for (int it = 0; it < 4; ++it) {
        int i = tid + it * 256;
        int r = i >> 4, k4 = i & 15;
        float4 a = *(const float4*)(emb + (rb + r) * 64 + k4 * 4);
        *(float4*)(&As[r][k4 * 4]) = a;
        float4 w = *(const float4*)(emb + (cb + r) * 64 + k4 * 4);
        Bs[k4 * 4 + 0][r] = w.x; Bs[k4 * 4 + 1][r] = w.y;
        Bs[k4 * 4 + 2][r] = w.z; Bs[k4 * 4 + 3][r] = w.w;
    }
    __syncthreads();
    const int ty = tid >> 4, tx = tid & 15;
    float acc[4][4] = {};
    #pragma unroll 8
    for (int k = 0; k < 64; ++k) {
        float a[4], b[4];
        #pragma unroll
        for (int i = 0; i < 4; ++i) a[i] = As[ty * 4 + i][k];
        #pragma unroll
        for (int j = 0; j < 4; ++j) b[j] = Bs[k][tx + 16 * j];
        #pragma unroll
        for (int i = 0; i < 4; ++i)
            #pragma unroll
            for (int j = 0; j < 4; ++j) acc[i][j] = fmaf(a[i], b[j], acc[i][j]);
    }
    #pragma unroll
    for (int i = 0; i < 4; ++i)
        #pragma unroll
        for (int j = 0; j < 4; ++j)
            g_EE[(rb + ty * 4 + i) * N_DIM + cb + tx + 16 * j] = acc[i][j];
}

// ---------------------------------------------------------------------------
// k_diag: D[bt][n] = ||x_btn||^2 + EE[n][n]
// ---------------------------------------------------------------------------
__global__ void k_diag(const float* __restrict__ ori) {
    const int bt = blockIdx.y;
    const int b = bt / T_DIM, t = bt % T_DIM;
    const int tid = threadIdx.x;
    const int rloc = tid >> 4, q = tid & 15;
    const int n = blockIdx.x * 16 + rloc;
    const size_t g = (size_t)b * 786432 + (size_t)n * 1536 + (size_t)t * 64 + q * 4;
    float4 v = *(const float4*)(ori + g);
    float s = v.x * v.x + v.y * v.y + v.z * v.z + v.w * v.w;
    #pragma unroll
    for (int o = 8; o > 0; o >>= 1) s += __shfl_xor_sync(0xffffffffu, s, o);
    if (q == 0)
        g_D[(size_t)bt * N_DIM + n] = s + g_EE[(size_t)n * N_DIM + n];
}

// ---------------------------------------------------------------------------
// k_vw: [X;U](1024x64) @ W^T(64x64) per bt; dup-A smem, FFMA2, 24-op loop.
// grid.x = 8 slabs of 128 rows; slabs 0-3 from ori, 4-7 from unc.
// ---------------------------------------------------------------------------
__global__ __launch_bounds__(256, 2) void k_vw(const float* __restrict__ ori,
                                               const float* __restrict__ unc,
                                               const float* __restrict__ W1) {
    extern __shared__ float sm[];
    float (*As2)[A2P] = (float(*)[A2P])sm;          // (k, 2r-dup) 64 x 260
    float (*Ws)[WP]   = (float(*)[WP])(sm + 64 * A2P);  // (k, o) 64 x 66
    const int slab = blockIdx.x, bt = blockIdx.y;
    const int b = bt / T_DIM, t = bt % T_DIM;
    const int tid = threadIdx.x;
    const bool isU = slab >= 4;
    const int n0 = (slab & 3) * 128;
    const float* src = isU ? unc : ori;
    const size_t base = (size_t)b * 786432 + (size_t)t * 64;

    #pragma unroll
    for (int it = 0; it < 8; ++it) {
        int i = tid + it * 256;
        int r = i >> 4, q = i & 15;
        float4 v = *(const float4*)(src + base + (size_t)(n0 + r) * 1536 + q * 4);
        *(u64*)(&As2[q * 4 + 0][2 * r]) = pack2(v.x, v.x);
        *(u64*)(&As2[q * 4 + 1][2 * r]) = pack2(v.y, v.y);
        *(u64*)(&As2[q * 4 + 2][2 * r]) = pack2(v.z, v.z);
        *(u64*)(&As2[q * 4 + 3][2 * r]) = pack2(v.w, v.w);
    }
    #pragma unroll
    for (int it = 0; it < 4; ++it) {
        int i = tid + it * 256;
        int o = i >> 4, q = i & 15;
        float4 w = *(const float4*)(W1 + o * 64 + q * 4);
        Ws[q * 4 + 0][o] = w.x; Ws[q * 4 + 1][o] = w.y;
        Ws[q * 4 + 2][o] = w.z; Ws[q * 4 + 3][o] = w.w;
    }
    __syncthreads();

    const int ty = tid >> 3, tx = tid & 7;  // 32 x 8
    u64 acc[4][4] = {};
    #pragma unroll 8
    for (int k = 0; k < 64; ++k) {
        u64 bp[4];
        #pragma unroll
        for (int j = 0; j < 4; ++j) bp[j] = *(const u64*)(&Ws[k][2 * tx + 16 * j]);
        #pragma unroll
        for (int i = 0; i < 4; ++i) {
            u64 ad = *(const u64*)(&As2[k][2 * (ty + 32 * i)]);
            #pragma unroll
            for (int j = 0; j < 4; ++j) acc[i][j] = ffma2(ad, bp[j], acc[i][j]);
        }
    }
    #pragma unroll
    for (int i = 0; i < 4; ++i) {
        int n = n0 + ty + 32 * i;
        size_t row = ((size_t)bt * N_DIM + n) * 128 + (isU ? 64 : 0);
        #pragma unroll
        for (int j = 0; j < 4; ++j) {
            float2 v = unpack2(acc[i][j]);
            *(float2*)(g_VW + row + 2 * tx + 16 * j) = v;
        }
    }
}

// ---------------------------------------------------------------------------
// k_logits: E = exp(relu(X@X^T + EE) - D); dup-A smem, FFMA2, 44-op loop.
// 128x128 tile, K=64 one pass. Deterministic row-sum partials.
// ---------------------------------------------------------------------------
__global__ __launch_bounds__(256, 2) void k_logits(const float* __restrict__ ori) {
    extern __shared__ float sm[];
    float (*As2)[A2P] = (float(*)[A2P])sm;             // (k, 2r-dup) 64 x 260
    float (*Bs)[BP]   = (float(*)[BP])(sm + 64 * A2P); // (k, c)      64 x 130
    const int bx = blockIdx.x;
    const int cb = bx * 128, rb = blockIdx.y * 128, bt = blockIdx.z;
    const int b = bt / T_DIM, t = bt % T_DIM;
    const int tid = threadIdx.x;
    const size_t base = (size_t)b * 786432 + (size_t)t * 64;

    #pragma unroll
    for (int it = 0; it < 8; ++it) {
        int i = tid + it * 256;
        int r = i >> 4, q = i & 15;
        float4 v = *(const float4*)(ori + base + (size_t)(rb + r) * 1536 + q * 4);
        *(u64*)(&As2[q * 4 + 0][2 * r]) = pack2(v.x, v.x);
        *(u64*)(&As2[q * 4 + 1][2 * r]) = pack2(v.y, v.y);
        *(u64*)(&As2[q * 4 + 2][2 * r]) = pack2(v.z, v.z);
        *(u64*)(&As2[q * 4 + 3][2 * r]) = pack2(v.w, v.w);
    }
    #pragma unroll
    for (int it = 0; it < 8; ++it) {
        int i = tid + it * 256;
        int c = i >> 4, q = i & 15;
        float4 v = *(const float4*)(ori + base + (size_t)(cb + c) * 1536 + q * 4);
        Bs[q * 4 + 0][c] = v.x; Bs[q * 4 + 1][c] = v.y;
        Bs[q * 4 + 2][c] = v.z; Bs[q * 4 + 3][c] = v.w;
    }
    __syncthreads();

    const int ty = tid >> 4, tx = tid & 15;
    u64 acc[8][4] = {};
    #pragma unroll 8
    for (int k = 0; k < 64; ++k) {
        u64 bp[4];
        #pragma unroll
        for (int j = 0; j < 4; ++j) bp[j] = *(const u64*)(&Bs[k][2 * tx + 32 * j]);
        #pragma unroll
        for (int i = 0; i < 8; ++i) {
            u64 ad = *(const u64*)(&As2[k][2 * (ty + 16 * i)]);
            #pragma unroll
            for (int j = 0; j < 4; ++j) acc[i][j] = ffma2(ad, bp[j], acc[i][j]);
        }
    }

    #pragma unroll
    for (int i = 0; i < 8; ++i) {
        int r = rb + ty + 16 * i;
        float dr = g_D[(size_t)bt * N_DIM + r];
        size_t srow = ((size_t)bt * N_DIM + r) * N_DIM;
        float rsum = 0.0f;
        #pragma unroll
        for (int j = 0; j < 4; ++j) {
            int c = cb + 2 * tx + 32 * j;
            float2 e = *(const float2*)(g_EE + (size_t)r * N_DIM + c);
            float2 v = unpack2(acc[i][j]);
            float2 o;
            o.x = __expf(fmaxf(v.x + e.x, 0.0f) - dr);
            o.y = __expf(fmaxf(v.y + e.y, 0.0f) - dr);
            *(float2*)(g_S + srow + c) = o;
            rsum += o.x + o.y;
        }
        #pragma unroll
        for (int o = 8; o > 0; o >>= 1)
            rsum += __shfl_xor_sync(0xffffffffu, rsum, o);
        if (tx == 0)
            g_RSP[((size_t)bt * 4 + bx) * N_DIM + r] = rsum;
    }
}

// ---------------------------------------------------------------------------
// k_out: OUT = relu( (1/rowsum) * (E @ [XW|UW]) )
// 128x128 tile, K=512 in 8 chunks, f32x2 FMA.
// ---------------------------------------------------------------------------
__global__ __launch_bounds__(256, 2) void k_out(float* __restrict__ out, size_t uf_off) {
    extern __shared__ float sm[];
    float (*Ps)[AP] = (float(*)[AP])sm;                 // (r, k) 128x68
    float (*Vs)[VP] = (float(*)[VP])(sm + 128 * AP);    // (k, c) 64x132
    const int rb = blockIdx.x * 128, bt = blockIdx.y;
    const int b = bt / T_DIM, t = bt % T_DIM;
    const int tid = threadIdx.x;
    const int ty = tid >> 4, tx = tid & 15;

    u64 acc[8][4] = {};
    for (int kt = 0; kt < 8; ++kt) {
        #pragma unroll
        for (int it = 0; it < 8; ++it) {
            int i = tid + it * 256;
            int r = i >> 4, q = i & 15;
            *(float4*)(&Ps[r][q * 4]) = *(const float4*)(g_S +
                ((size_t)bt * N_DIM + rb + r) * N_DIM + kt * 64 + q * 4);
        }
        #pragma unroll
        for (int it = 0; it < 8; ++it) {
            int i = tid + it * 256;
            int k = i >> 5, q = i & 31;
            *(float4*)(&Vs[k][q * 4]) =
                *(const float4*)(g_VW + ((size_t)bt * N_DIM + kt * 64 + k) * 128 + q * 4);
        }
        __syncthreads();

        #pragma unroll 8
        for (int k = 0; k < 64; ++k) {
            u64 bp[4];
            #pragma unroll
            for (int j = 0; j < 4; ++j) bp[j] = *(const u64*)(&Vs[k][2 * tx + 32 * j]);
            #pragma unroll
            for (int i = 0; i < 8; ++i) {
                float a = Ps[ty + 16 * i][k];
                u64 ad = pack2(a, a);
                #pragma unroll
                for (int j = 0; j < 4; ++j) acc[i][j] = ffma2(ad, bp[j], acc[i][j]);
            }
        }
        __syncthreads();
    }

    #pragma unroll
    for (int i = 0; i < 8; ++i) {
        int n = rb + ty + 16 * i;
        size_t rsb = (size_t)bt * 4 * N_DIM + n;
        float rs = g_RSP[rsb] + g_RSP[rsb + N_DIM] +
                   g_RSP[rsb + 2 * N_DIM] + g_RSP[rsb + 3 * N_DIM];
        float inv = 1.0f / rs;
        size_t obase = (size_t)b * 786432 + (size_t)n * 1536 + (size_t)t * 64;
        #pragma unroll
        for (int j = 0; j < 4; ++j) {
            int c = 2 * tx + 32 * j;
            float2 v = unpack2(acc[i][j]);
            v.x = fmaxf(v.x * inv, 0.0f);
            v.y = fmaxf(v.y * inv, 0.0f);
            if (c < 64) *(float2*)(out + obase + c) = v;
            else        *(float2*)(out + uf_off + obase + (c - 64)) = v;
        }
    }
}

// ---------------------------------------------------------------------------
extern "C" void kernel_launch(void* const* d_in, const int* in_sizes, int n_in,
                              void* d_out, int out_size) {
    const float* ori = (const float*)d_in[0];   // (16,512,24,64)
    const float* unc = (const float*)d_in[1];   // (16,512,24,64)
    const float* emb = (const float*)d_in[2];   // (512,64)
    const float* W1  = (const float*)d_in[3];   // (64,64)
    float* out = (float*)d_out;                 // [of | uf]
    const size_t uf_off = (size_t)out_size / 2;

    const int SMEM_LOGITS = (64 * A2P + 64 * BP) * 4;   // 99840 B
    const int SMEM_VW     = (64 * A2P + 64 * WP) * 4;   // 83456 B
    const int SMEM_OUT    = (128 * AP + 64 * VP) * 4;   // 68608 B
    cudaFuncSetAttribute(k_logits, cudaFuncAttributeMaxDynamicSharedMemorySize, SMEM_LOGITS);
    cudaFuncSetAttribute(k_vw,     cudaFuncAttributeMaxDynamicSharedMemorySize, SMEM_VW);
    cudaFuncSetAttribute(k_out,    cudaFuncAttributeMaxDynamicSharedMemorySize, SMEM_OUT);

    k_ee<<<dim3(8, 8), 256>>>(emb);
    k_diag<<<dim3(32, BT_DIM), 256>>>(ori);
    k_vw<<<dim3(8, BT_DIM), 256, SMEM_VW>>>(ori, unc, W1);
    k_logits<<<dim3(4, 4, BT_DIM), 256, SMEM_LOGITS>>>(ori);
    k_out<<<dim3(4, BT_DIM), 256, SMEM_OUT>>>(out, uf_off);
}

// round 10
// speedup vs baseline: 1.6026x; 1.6026x over previous
#include <cuda_runtime.h>
#include <cuda_bf16.h>
#include <cstddef>
#include <cstdint>

// B=16, N=512, T=24, F=64, BT=384
#define T_DIM 24
#define N_DIM 512
#define BT_DIM 384

// Scratch (device globals: allocation-free per harness rules)
static __device__ float g_D[(size_t)BT_DIM * N_DIM];                         // diag shift
static __device__ float g_ED[N_DIM];                                         // ||emb_n||^2
static __device__ float g_RSP[(size_t)BT_DIM * 4 * N_DIM];                   // row-sum partials
static __device__ __nv_bfloat16 g_EMhi[N_DIM * 64];                          // emb hi
static __device__ __nv_bfloat16 g_EMlo[N_DIM * 64];                          // emb lo
static __device__ __nv_bfloat16 g_Xhi[(size_t)BT_DIM * N_DIM * 64];          // 25 MB
static __device__ __nv_bfloat16 g_Xlo[(size_t)BT_DIM * N_DIM * 64];          // 25 MB
static __device__ __nv_bfloat16 g_Shi[(size_t)BT_DIM * N_DIM * N_DIM];       // 201 MB
static __device__ __nv_bfloat16 g_Slo[(size_t)BT_DIM * N_DIM * N_DIM];       // 201 MB
static __device__ __nv_bfloat16 g_Vhi[(size_t)BT_DIM * 128 * N_DIM];         // 50 MB
static __device__ __nv_bfloat16 g_Vlo[(size_t)BT_DIM * 128 * N_DIM];         // 50 MB

typedef unsigned long long u64;
__device__ __forceinline__ u64 pack2(float lo, float hi) {
    u64 r; asm("mov.b64 %0, {%1, %2};" : "=l"(r) : "f"(lo), "f"(hi)); return r;
}
__device__ __forceinline__ u64 ffma2(u64 a, u64 b, u64 c) {
    u64 d; asm("fma.rn.f32x2 %0, %1, %2, %3;" : "=l"(d) : "l"(a), "l"(b), "l"(c)); return d;
}
__device__ __forceinline__ float2 unpack2(u64 v) {
    float2 r; asm("mov.b64 {%0, %1}, %2;" : "=f"(r.x), "=f"(r.y) : "l"(v)); return r;
}

// ---- warp-level tensor core plumbing (sm_80 baseline PTX: works on sm_103) --
__device__ __forceinline__ uint32_t smem_u32(const void* p) {
    uint32_t a;
    asm("{ .reg .u64 t; cvta.to.shared.u64 t, %1; cvt.u32.u64 %0, t; }" : "=r"(a) : "l"(p));
    return a;
}
__device__ __forceinline__ void ldm4(uint32_t addr, uint32_t* r) {
    asm volatile("ldmatrix.sync.aligned.m8n8.x4.shared.b16 {%0,%1,%2,%3}, [%4];"
                 : "=r"(r[0]), "=r"(r[1]), "=r"(r[2]), "=r"(r[3]) : "r"(addr));
}
__device__ __forceinline__ void mma16816(float* d, const uint32_t* a, const uint32_t* b) {
    asm volatile("mma.sync.aligned.m16n8k16.row.col.f32.bf16.bf16.f32 "
        "{%0,%1,%2,%3}, {%4,%5,%6,%7}, {%8,%9}, {%0,%1,%2,%3};"
        : "+f"(d[0]), "+f"(d[1]), "+f"(d[2]), "+f"(d[3])
        : "r"(a[0]), "r"(a[1]), "r"(a[2]), "r"(a[3]), "r"(b[0]), "r"(b[1]));
}
// SW128 swizzle for 128B-pitch tiles
__device__ __forceinline__ uint32_t swadr(uint32_t base, int row, int colb) {
    uint32_t off = row * 128 + colb;
    return base + (off ^ ((off >> 3) & 0x70));
}

// ---------------------------------------------------------------------------
// k_embprep: emb -> bf16 hi/lo, g_ED[n] = ||emb_n||^2
// ---------------------------------------------------------------------------
__global__ void k_embprep(const float* __restrict__ emb) {
    const int tid = threadIdx.x;
    const int rl = tid >> 2, q = tid & 3;
    const int n = blockIdx.x * 64 + rl;
    const float* src = emb + n * 64 + q * 16;
    float ss = 0.0f;
    __align__(16) __nv_bfloat16 hb[16], lb[16];
    #pragma unroll
    for (int i = 0; i < 4; ++i) {
        float4 v = ((const float4*)src)[i];
        float vv[4] = {v.x, v.y, v.z, v.w};
        #pragma unroll
        for (int j = 0; j < 4; ++j) {
            ss += vv[j] * vv[j];
            __nv_bfloat16 h = __float2bfloat16(vv[j]);
            hb[i * 4 + j] = h;
            lb[i * 4 + j] = __float2bfloat16(vv[j] - __bfloat162float(h));
        }
    }
    size_t xo = (size_t)n * 64 + q * 16;
    ((uint4*)(g_EMhi + xo))[0] = ((uint4*)hb)[0];
    ((uint4*)(g_EMhi + xo))[1] = ((uint4*)hb)[1];
    ((uint4*)(g_EMlo + xo))[0] = ((uint4*)lb)[0];
    ((uint4*)(g_EMlo + xo))[1] = ((uint4*)lb)[1];
    ss += __shfl_xor_sync(0xffffffffu, ss, 1);
    ss += __shfl_xor_sync(0xffffffffu, ss, 2);
    if (q == 0) g_ED[n] = ss;
}

// ---------------------------------------------------------------------------
// k_prep: X -> bf16 hi/lo (per-bt layout), D[bt][n] = ||x||^2 + ||emb_n||^2
// ---------------------------------------------------------------------------
__global__ void k_prep(const float* __restrict__ ori) {
    const int bt = blockIdx.y, b = bt / T_DIM, t = bt % T_DIM;
    const int tid = threadIdx.x;
    const int rl = tid >> 2, q = tid & 3;
    const int n = blockIdx.x * 64 + rl;
    const float* src = ori + (size_t)b * 786432 + (size_t)n * 1536 + (size_t)t * 64 + q * 16;
    float ss = 0.0f;
    __align__(16) __nv_bfloat16 hb[16], lb[16];
    #pragma unroll
    for (int i = 0; i < 4; ++i) {
        float4 v = ((const float4*)src)[i];
        float vv[4] = {v.x, v.y, v.z, v.w};
        #pragma unroll
        for (int j = 0; j < 4; ++j) {
            ss += vv[j] * vv[j];
            __nv_bfloat16 h = __float2bfloat16(vv[j]);
            hb[i * 4 + j] = h;
            lb[i * 4 + j] = __float2bfloat16(vv[j] - __bfloat162float(h));
        }
    }
    size_t xo = ((size_t)bt * N_DIM + n) * 64 + q * 16;
    ((uint4*)(g_Xhi + xo))[0] = ((uint4*)hb)[0];
    ((uint4*)(g_Xhi + xo))[1] = ((uint4*)hb)[1];
    ((uint4*)(g_Xlo + xo))[0] = ((uint4*)lb)[0];
    ((uint4*)(g_Xlo + xo))[1] = ((uint4*)lb)[1];
    ss += __shfl_xor_sync(0xffffffffu, ss, 1);
    ss += __shfl_xor_sync(0xffffffffu, ss, 2);
    if (q == 0)
        g_D[(size_t)bt * N_DIM + n] = ss + g_ED[n];
}

// ---------------------------------------------------------------------------
// k_vwt: Vt[bt][c][n] = (W1 @ srcT); c<64 from X, c>=64 from U; bf16 hi/lo out.
// ---------------------------------------------------------------------------
#define VWP 130
__global__ __launch_bounds__(256, 2) void k_vwt(const float* __restrict__ ori,
                                                const float* __restrict__ unc,
                                                const float* __restrict__ W1) {
    extern __shared__ float sm[];
    float (*Ws)[66]  = (float(*)[66])sm;              // (f, c) 64x66
    float (*Bs)[VWP] = (float(*)[VWP])(sm + 64 * 66); // (f, n) 64x130
    const int sx = blockIdx.x, bt = blockIdx.y;
    const int isU = sx >> 2, nc = sx & 3;
    const int n0 = nc * 128;
    const int b = bt / T_DIM, t = bt % T_DIM;
    const int tid = threadIdx.x;
    const float* src = isU ? unc : ori;
    const size_t base = (size_t)b * 786432 + (size_t)t * 64;

    #pragma unroll
    for (int it = 0; it < 4; ++it) {
        int i = tid + it * 256;
        int o = i >> 4, q = i & 15;
        float4 w = *(const float4*)(W1 + o * 64 + q * 4);
        Ws[q * 4 + 0][o] = w.x; Ws[q * 4 + 1][o] = w.y;
        Ws[q * 4 + 2][o] = w.z; Ws[q * 4 + 3][o] = w.w;
    }
    #pragma unroll
    for (int it = 0; it < 8; ++it) {
        int i = tid + it * 256;
        int r = i >> 4, q = i & 15;
        float4 v = *(const float4*)(src + base + (size_t)(n0 + r) * 1536 + q * 4);
        Bs[q * 4 + 0][r] = v.x; Bs[q * 4 + 1][r] = v.y;
        Bs[q * 4 + 2][r] = v.z; Bs[q * 4 + 3][r] = v.w;
    }
    __syncthreads();

    const int ty = tid >> 4, tx = tid & 15;
    u64 acc[4][4] = {};
    #pragma unroll 8
    for (int k = 0; k < 64; ++k) {
        u64 bp[4];
        #pragma unroll
        for (int j = 0; j < 4; ++j) bp[j] = *(const u64*)(&Bs[k][2 * tx + 32 * j]);
        #pragma unroll
        for (int i2 = 0; i2 < 4; ++i2) {
            float a = Ws[k][ty * 4 + i2];
            u64 ad = pack2(a, a);
            #pragma unroll
            for (int j = 0; j < 4; ++j) acc[i2][j] = ffma2(ad, bp[j], acc[i2][j]);
        }
    }
    #pragma unroll
    for (int i2 = 0; i2 < 4; ++i2) {
        size_t row = (size_t)bt * 128 + isU * 64 + ty * 4 + i2;
        #pragma unroll
        for (int j = 0; j < 4; ++j) {
            float2 v = unpack2(acc[i2][j]);
            __nv_bfloat16 hx = __float2bfloat16(v.x), hy = __float2bfloat16(v.y);
            __nv_bfloat162 h2; h2.x = hx; h2.y = hy;
            __nv_bfloat162 l2;
            l2.x = __float2bfloat16(v.x - __bfloat162float(hx));
            l2.y = __float2bfloat16(v.y - __bfloat162float(hy));
            int n = n0 + 2 * tx + 32 * j;
            *(__nv_bfloat162*)(g_Vhi + row * N_DIM + n) = h2;
            *(__nv_bfloat162*)(g_Vlo + row * N_DIM + n) = l2;
        }
    }
}

// ---------------------------------------------------------------------------
// k_logits_tc: S-tile(128x128) = [X|emb] @ [X|emb]^T via mma.sync bf16 3-split,
// K=128 (k-tiles 0-3 from X, 4-7 from emb). Epilogue: relu, exp(-D), split
// store to g_Shi/g_Slo, deterministic row-sum partials.
// ---------------------------------------------------------------------------
#define LT_RS 131072
#define SMEM_LT (131072 + 2048)
__global__ __launch_bounds__(256, 1) void k_logits_tc() {
    extern __shared__ char smc[];
    const int cbi = blockIdx.x, rbi = blockIdx.y, bt = blockIdx.z;
    const int cb = cbi * 128, rb = rbi * 128;
    const int tid = threadIdx.x;
    const int wid = tid >> 5, lane = tid & 31;

    // 8 tiles of 128 rows x 64 bf16 (128B pitch, SW128): AXh AXl AEh AEl BXh BXl BEh BEl
    const size_t xb = (size_t)bt * N_DIM * 64;
    const __nv_bfloat16* srcs[8] = {
        g_Xhi + xb + (size_t)rb * 64, g_Xlo + xb + (size_t)rb * 64,
        g_EMhi + (size_t)rb * 64,     g_EMlo + (size_t)rb * 64,
        g_Xhi + xb + (size_t)cb * 64, g_Xlo + xb + (size_t)cb * 64,
        g_EMhi + (size_t)cb * 64,     g_EMlo + (size_t)cb * 64,
    };
    #pragma unroll
    for (int tile = 0; tile < 8; ++tile) {
        char* dst = smc + tile * 16384;
        const __nv_bfloat16* sp = srcs[tile];
        #pragma unroll
        for (int it = 0; it < 4; ++it) {
            int i = tid + it * 256;
            int row = i >> 3, q = i & 7;
            uint32_t off = (uint32_t)(row * 128 + q * 16);
            off ^= (off >> 3) & 0x70;
            *(uint4*)(dst + off) = *(const uint4*)(sp + (size_t)row * 64 + q * 8);
        }
    }
    __syncthreads();

    const uint32_t sbase = smem_u32(smc);
    const int wm = (wid & 1) * 64, wn = (wid >> 1) * 32;
    const int mat = lane >> 3, rl = lane & 7;
    float acc[4][4][4] = {};

    #pragma unroll
    for (int kk = 0; kk < 8; ++kk) {
        const int sel = kk >> 2, kb = (kk & 3) * 32;
        const uint32_t aH = sbase + (sel ? 2 : 0) * 16384;
        const uint32_t aL = sbase + (sel ? 3 : 1) * 16384;
        const uint32_t bH = sbase + (sel ? 6 : 4) * 16384;
        const uint32_t bL = sbase + (sel ? 7 : 5) * 16384;
        uint32_t Ah[4][4], Al[4][4], Bh[4][2], Bl[4][2];
        #pragma unroll
        for (int mi = 0; mi < 4; ++mi) {
            int row = wm + mi * 16 + (mat & 1) * 8 + rl;
            int col = kb + (mat >> 1) * 16;
            ldm4(swadr(aH, row, col), Ah[mi]);
            ldm4(swadr(aL, row, col), Al[mi]);
        }
        #pragma unroll
        for (int g = 0; g < 2; ++g) {
            int nrow = wn + g * 16 + (mat >> 1) * 8 + rl;
            int col = kb + (mat & 1) * 16;
            uint32_t th[4], tl[4];
            ldm4(swadr(bH, nrow, col), th);
            ldm4(swadr(bL, nrow, col), tl);
            Bh[2 * g][0] = th[0]; Bh[2 * g][1] = th[1];
            Bh[2 * g + 1][0] = th[2]; Bh[2 * g + 1][1] = th[3];
            Bl[2 * g][0] = tl[0]; Bl[2 * g][1] = tl[1];
            Bl[2 * g + 1][0] = tl[2]; Bl[2 * g + 1][1] = tl[3];
        }
        #pragma unroll
        for (int mi = 0; mi < 4; ++mi)
            #pragma unroll
            for (int ni = 0; ni < 4; ++ni) {
                mma16816(acc[mi][ni], Ah[mi], Bh[ni]);
                mma16816(acc[mi][ni], Ah[mi], Bl[ni]);
                mma16816(acc[mi][ni], Al[mi], Bh[ni]);
            }
    }

    // Epilogue
    float* rs = (float*)(smc + LT_RS);  // [4 warp_n][128 rows]
    #pragma unroll
    for (int mi = 0; mi < 4; ++mi) {
        #pragma unroll
        for (int h = 0; h < 2; ++h) {
            int rloc = wm + mi * 16 + h * 8 + (lane >> 2);
            int r = rb + rloc;
            float dr = g_D[(size_t)bt * N_DIM + r];
            __nv_bfloat16* sh = g_Shi + ((size_t)bt * N_DIM + r) * N_DIM + cb + wn;
            __nv_bfloat16* sl = g_Slo + ((size_t)bt * N_DIM + r) * N_DIM + cb + wn;
            float rsum = 0.0f;
            #pragma unroll
            for (int ni = 0; ni < 4; ++ni) {
                float p0 = __expf(fmaxf(acc[mi][ni][h * 2 + 0], 0.0f) - dr);
                float p1 = __expf(fmaxf(acc[mi][ni][h * 2 + 1], 0.0f) - dr);
                rsum += p0 + p1;
                __nv_bfloat162 hh, ll;
                hh.x = __float2bfloat16(p0);
                hh.y = __float2bfloat16(p1);
                ll.x = __float2bfloat16(p0 - __bfloat162float(hh.x));
                ll.y = __float2bfloat16(p1 - __bfloat162float(hh.y));
                int c = ni * 8 + (lane & 3) * 2;
                *(__nv_bfloat162*)(sh + c) = hh;
                *(__nv_bfloat162*)(sl + c) = ll;
            }
            rsum += __shfl_xor_sync(0xffffffffu, rsum, 1);
            rsum += __shfl_xor_sync(0xffffffffu, rsum, 2);
            if ((lane & 3) == 0) rs[(wid >> 1) * 128 + rloc] = rsum;
        }
    }
    __syncthreads();
    if (tid < 128) {
        float tot = rs[tid] + rs[128 + tid] + rs[256 + tid] + rs[384 + tid];
        g_RSP[((size_t)bt * 4 + cbi) * N_DIM + rb + tid] = tot;
    }
}

// ---------------------------------------------------------------------------
// k_out_tc: OUT-tile(128 rows x 128 ch) = relu(inv_rs * (E @ Vt^T));
// K=512 in 8 chunks, mma.sync bf16 3-split.
// ---------------------------------------------------------------------------
#define SMEM_OT 65536
__global__ __launch_bounds__(256, 1) void k_out_tc(float* __restrict__ out, size_t uf_off) {
    extern __shared__ char smc[];
    const int rbi = blockIdx.x, bt = blockIdx.y;
    const int rb = rbi * 128;
    const int b = bt / T_DIM, t = bt % T_DIM;
    const int tid = threadIdx.x;
    const int wid = tid >> 5, lane = tid & 31;
    const uint32_t sbase = smem_u32(smc);
    const int wm = (wid & 1) * 64, wn = (wid >> 1) * 32;
    const int mat = lane >> 3, rl = lane & 7;
    float acc[4][4][4] = {};

    for (int kt = 0; kt < 8; ++kt) {
        const __nv_bfloat16* srcs[4] = {
            g_Shi + ((size_t)bt * N_DIM + rb) * N_DIM + kt * 64,
            g_Slo + ((size_t)bt * N_DIM + rb) * N_DIM + kt * 64,
            g_Vhi + ((size_t)bt * 128) * N_DIM + kt * 64,
            g_Vlo + ((size_t)bt * 128) * N_DIM + kt * 64,
        };
        #pragma unroll
        for (int tile = 0; tile < 4; ++tile) {
            char* dst = smc + tile * 16384;
            const __nv_bfloat16* sp = srcs[tile];
            #pragma unroll
            for (int it = 0; it < 4; ++it) {
                int i = tid + it * 256;
                int row = i >> 3, q = i & 7;
                uint32_t off = (uint32_t)(row * 128 + q * 16);
                off ^= (off >> 3) & 0x70;
                *(uint4*)(dst + off) = *(const uint4*)(sp + (size_t)row * N_DIM + q * 8);
            }
        }
        __syncthreads();

        #pragma unroll
        for (int kk = 0; kk < 4; ++kk) {
            const int kb = kk * 32;
            uint32_t Ah[4][4], Al[4][4], Bh[4][2], Bl[4][2];
            #pragma unroll
            for (int mi = 0; mi < 4; ++mi) {
                int row = wm + mi * 16 + (mat & 1) * 8 + rl;
                int col = kb + (mat >> 1) * 16;
                ldm4(swadr(sbase, row, col), Ah[mi]);
                ldm4(swadr(sbase + 16384, row, col), Al[mi]);
            }
            #pragma unroll
            for (int g = 0; g < 2; ++g) {
                int nrow = wn + g * 16 + (mat >> 1) * 8 + rl;
                int col = kb + (mat & 1) * 16;
                uint32_t th[4], tl[4];
                ldm4(swadr(sbase + 32768, nrow, col), th);
                ldm4(swadr(sbase + 49152, nrow, col), tl);
                Bh[2 * g][0] = th[0]; Bh[2 * g][1] = th[1];
                Bh[2 * g + 1][0] = th[2]; Bh[2 * g + 1][1] = th[3];
                Bl[2 * g][0] = tl[0]; Bl[2 * g][1] = tl[1];
                Bl[2 * g + 1][0] = tl[2]; Bl[2 * g + 1][1] = tl[3];
            }
            #pragma unroll
            for (int mi = 0; mi < 4; ++mi)
                #pragma unroll
                for (int ni = 0; ni < 4; ++ni) {
                    mma16816(acc[mi][ni], Ah[mi], Bh[ni]);
                    mma16816(acc[mi][ni], Ah[mi], Bl[ni]);
                    mma16816(acc[mi][ni], Al[mi], Bh[ni]);
                }
        }
        __syncthreads();
    }

    // Epilogue: normalize by row sum, relu, scatter to (B,N,T,F) of/uf
    #pragma unroll
    for (int mi = 0; mi < 4; ++mi) {
        #pragma unroll
        for (int h = 0; h < 2; ++h) {
            int n = rb + wm + mi * 16 + h * 8 + (lane >> 2);
            size_t rsb = (size_t)bt * 4 * N_DIM + n;
            float rsv = g_RSP[rsb] + g_RSP[rsb + N_DIM] +
                        g_RSP[rsb + 2 * N_DIM] + g_RSP[rsb + 3 * N_DIM];
            float inv = 1.0f / rsv;
            size_t obase = (size_t)b * 786432 + (size_t)n * 1536 + (size_t)t * 64;
            #pragma unroll
            for (int ni = 0; ni < 4; ++ni) {
                int ch = wn + ni * 8 + (lane & 3) * 2;
                float2 v;
                v.x = fmaxf(acc[mi][ni][h * 2 + 0] * inv, 0.0f);
                v.y = fmaxf(acc[mi][ni][h * 2 + 1] * inv, 0.0f);
                if (ch < 64) *(float2*)(out + obase + ch) = v;
                else         *(float2*)(out + uf_off + obase + (ch - 64)) = v;
            }
        }
    }
}

// ---------------------------------------------------------------------------
extern "C" void kernel_launch(void* const* d_in, const int* in_sizes, int n_in,
                              void* d_out, int out_size) {
    const float* ori = (const float*)d_in[0];   // (16,512,24,64)
    const float* unc = (const float*)d_in[1];   // (16,512,24,64)
    const float* emb = (const float*)d_in[2];   // (512,64)
    const float* W1  = (const float*)d_in[3];   // (64,64)
    float* out = (float*)d_out;                 // [of | uf]
    const size_t uf_off = (size_t)out_size / 2;

    const int SMEM_VWT = (64 * 66 + 64 * VWP) * 4;  // 50176 B
    cudaFuncSetAttribute(k_vwt, cudaFuncAttributeMaxDynamicSharedMemorySize, SMEM_VWT);
    cudaFuncSetAttribute(k_logits_tc, cudaFuncAttributeMaxDynamicSharedMemorySize, SMEM_LT);
    cudaFuncSetAttribute(k_out_tc, cudaFuncAttributeMaxDynamicSharedMemorySize, SMEM_OT);

    k_embprep<<<8, 256>>>(emb);
    k_prep<<<dim3(8, BT_DIM), 256>>>(ori);
    k_vwt<<<dim3(8, BT_DIM), 256, SMEM_VWT>>>(ori, unc, W1);
    k_logits_tc<<<dim3(4, 4, BT_DIM), 256, SMEM_LT>>>();
    k_out_tc<<<dim3(4, BT_DIM), 256, SMEM_OT>>>(out, uf_off);
}

// round 11
// speedup vs baseline: 1.7692x; 1.1039x over previous
#include <cuda_runtime.h>
#include <cuda_bf16.h>
#include <cstddef>
#include <cstdint>

// B=16, N=512, T=24, F=64, BT=384
#define T_DIM 24
#define N_DIM 512
#define BT_DIM 384

// Scratch (device globals: allocation-free per harness rules)
static __device__ float g_D[(size_t)BT_DIM * N_DIM];                         // diag shift
static __device__ float g_ED[N_DIM];                                         // ||emb_n||^2
static __device__ float g_RSP[(size_t)BT_DIM * 4 * N_DIM];                   // row-sum partials
static __device__ __nv_bfloat16 g_EMhi[N_DIM * 64];                          // emb hi
static __device__ __nv_bfloat16 g_EMlo[N_DIM * 64];                          // emb lo
static __device__ __nv_bfloat16 g_Xhi[(size_t)BT_DIM * N_DIM * 64];          // 25 MB
static __device__ __nv_bfloat16 g_Xlo[(size_t)BT_DIM * N_DIM * 64];          // 25 MB
static __device__ __nv_bfloat16 g_Shi[(size_t)BT_DIM * N_DIM * N_DIM];       // 201 MB
static __device__ __nv_bfloat16 g_Slo[(size_t)BT_DIM * N_DIM * N_DIM];       // 201 MB
static __device__ __nv_bfloat16 g_Vhi[(size_t)BT_DIM * 128 * N_DIM];         // 50 MB
static __device__ __nv_bfloat16 g_Vlo[(size_t)BT_DIM * 128 * N_DIM];         // 50 MB

typedef unsigned long long u64;
__device__ __forceinline__ u64 pack2(float lo, float hi) {
    u64 r; asm("mov.b64 %0, {%1, %2};" : "=l"(r) : "f"(lo), "f"(hi)); return r;
}
__device__ __forceinline__ u64 ffma2(u64 a, u64 b, u64 c) {
    u64 d; asm("fma.rn.f32x2 %0, %1, %2, %3;" : "=l"(d) : "l"(a), "l"(b), "l"(c)); return d;
}
__device__ __forceinline__ float2 unpack2(u64 v) {
    float2 r; asm("mov.b64 {%0, %1}, %2;" : "=f"(r.x), "=f"(r.y) : "l"(v)); return r;
}

// ---- warp-level tensor core plumbing (sm_80 baseline PTX) ------------------
__device__ __forceinline__ uint32_t smem_u32(const void* p) {
    uint32_t a;
    asm("{ .reg .u64 t; cvta.to.shared.u64 t, %1; cvt.u32.u64 %0, t; }" : "=r"(a) : "l"(p));
    return a;
}
__device__ __forceinline__ void ldm4(uint32_t addr, uint32_t* r) {
    asm volatile("ldmatrix.sync.aligned.m8n8.x4.shared.b16 {%0,%1,%2,%3}, [%4];"
                 : "=r"(r[0]), "=r"(r[1]), "=r"(r[2]), "=r"(r[3]) : "r"(addr));
}
__device__ __forceinline__ void mma16816(float* d, const uint32_t* a, const uint32_t* b) {
    asm volatile("mma.sync.aligned.m16n8k16.row.col.f32.bf16.bf16.f32 "
        "{%0,%1,%2,%3}, {%4,%5,%6,%7}, {%8,%9}, {%0,%1,%2,%3};"
        : "+f"(d[0]), "+f"(d[1]), "+f"(d[2]), "+f"(d[3])
        : "r"(a[0]), "r"(a[1]), "r"(a[2]), "r"(a[3]), "r"(b[0]), "r"(b[1]));
}
// SW128 swizzle for 128B-pitch tiles
__device__ __forceinline__ uint32_t swadr(uint32_t base, int row, int colb) {
    uint32_t off = row * 128 + colb;
    return base + (off ^ ((off >> 3) & 0x70));
}

// ---------------------------------------------------------------------------
// k_embprep: emb -> bf16 hi/lo, g_ED[n] = ||emb_n||^2
// ---------------------------------------------------------------------------
__global__ void k_embprep(const float* __restrict__ emb) {
    const int tid = threadIdx.x;
    const int rl = tid >> 2, q = tid & 3;
    const int n = blockIdx.x * 64 + rl;
    const float* src = emb + n * 64 + q * 16;
    float ss = 0.0f;
    __align__(16) __nv_bfloat16 hb[16], lb[16];
    #pragma unroll
    for (int i = 0; i < 4; ++i) {
        float4 v = ((const float4*)src)[i];
        float vv[4] = {v.x, v.y, v.z, v.w};
        #pragma unroll
        for (int j = 0; j < 4; ++j) {
            ss += vv[j] * vv[j];
            __nv_bfloat16 h = __float2bfloat16(vv[j]);
            hb[i * 4 + j] = h;
            lb[i * 4 + j] = __float2bfloat16(vv[j] - __bfloat162float(h));
        }
    }
    size_t xo = (size_t)n * 64 + q * 16;
    ((uint4*)(g_EMhi + xo))[0] = ((uint4*)hb)[0];
    ((uint4*)(g_EMhi + xo))[1] = ((uint4*)hb)[1];
    ((uint4*)(g_EMlo + xo))[0] = ((uint4*)lb)[0];
    ((uint4*)(g_EMlo + xo))[1] = ((uint4*)lb)[1];
    ss += __shfl_xor_sync(0xffffffffu, ss, 1);
    ss += __shfl_xor_sync(0xffffffffu, ss, 2);
    if (q == 0) g_ED[n] = ss;
}

// ---------------------------------------------------------------------------
// k_prep: X -> bf16 hi/lo (per-bt layout), D[bt][n] = ||x||^2 + ||emb_n||^2
// ---------------------------------------------------------------------------
__global__ void k_prep(const float* __restrict__ ori) {
    const int bt = blockIdx.y, b = bt / T_DIM, t = bt % T_DIM;
    const int tid = threadIdx.x;
    const int rl = tid >> 2, q = tid & 3;
    const int n = blockIdx.x * 64 + rl;
    const float* src = ori + (size_t)b * 786432 + (size_t)n * 1536 + (size_t)t * 64 + q * 16;
    float ss = 0.0f;
    __align__(16) __nv_bfloat16 hb[16], lb[16];
    #pragma unroll
    for (int i = 0; i < 4; ++i) {
        float4 v = ((const float4*)src)[i];
        float vv[4] = {v.x, v.y, v.z, v.w};
        #pragma unroll
        for (int j = 0; j < 4; ++j) {
            ss += vv[j] * vv[j];
            __nv_bfloat16 h = __float2bfloat16(vv[j]);
            hb[i * 4 + j] = h;
            lb[i * 4 + j] = __float2bfloat16(vv[j] - __bfloat162float(h));
        }
    }
    size_t xo = ((size_t)bt * N_DIM + n) * 64 + q * 16;
    ((uint4*)(g_Xhi + xo))[0] = ((uint4*)hb)[0];
    ((uint4*)(g_Xhi + xo))[1] = ((uint4*)hb)[1];
    ((uint4*)(g_Xlo + xo))[0] = ((uint4*)lb)[0];
    ((uint4*)(g_Xlo + xo))[1] = ((uint4*)lb)[1];
    ss += __shfl_xor_sync(0xffffffffu, ss, 1);
    ss += __shfl_xor_sync(0xffffffffu, ss, 2);
    if (q == 0)
        g_D[(size_t)bt * N_DIM + n] = ss + g_ED[n];
}

// ---------------------------------------------------------------------------
// k_vwt: Vt[bt][c][n] = (W1 @ srcT); c<64 from X, c>=64 from U; bf16 hi/lo out.
// ---------------------------------------------------------------------------
#define VWP 130
__global__ __launch_bounds__(256, 2) void k_vwt(const float* __restrict__ ori,
                                                const float* __restrict__ unc,
                                                const float* __restrict__ W1) {
    extern __shared__ float sm[];
    float (*Ws)[66]  = (float(*)[66])sm;              // (f, c) 64x66
    float (*Bs)[VWP] = (float(*)[VWP])(sm + 64 * 66); // (f, n) 64x130
    const int sx = blockIdx.x, bt = blockIdx.y;
    const int isU = sx >> 2, nc = sx & 3;
    const int n0 = nc * 128;
    const int b = bt / T_DIM, t = bt % T_DIM;
    const int tid = threadIdx.x;
    const float* src = isU ? unc : ori;
    const size_t base = (size_t)b * 786432 + (size_t)t * 64;

    #pragma unroll
    for (int it = 0; it < 4; ++it) {
        int i = tid + it * 256;
        int o = i >> 4, q = i & 15;
        float4 w = *(const float4*)(W1 + o * 64 + q * 4);
        Ws[q * 4 + 0][o] = w.x; Ws[q * 4 + 1][o] = w.y;
        Ws[q * 4 + 2][o] = w.z; Ws[q * 4 + 3][o] = w.w;
    }
    #pragma unroll
    for (int it = 0; it < 8; ++it) {
        int i = tid + it * 256;
        int r = i >> 4, q = i & 15;
        float4 v = *(const float4*)(src + base + (size_t)(n0 + r) * 1536 + q * 4);
        Bs[q * 4 + 0][r] = v.x; Bs[q * 4 + 1][r] = v.y;
        Bs[q * 4 + 2][r] = v.z; Bs[q * 4 + 3][r] = v.w;
    }
    __syncthreads();

    const int ty = tid >> 4, tx = tid & 15;
    u64 acc[4][4] = {};
    #pragma unroll 8
    for (int k = 0; k < 64; ++k) {
        u64 bp[4];
        #pragma unroll
        for (int j = 0; j < 4; ++j) bp[j] = *(const u64*)(&Bs[k][2 * tx + 32 * j]);
        #pragma unroll
        for (int i2 = 0; i2 < 4; ++i2) {
            float a = Ws[k][ty * 4 + i2];
            u64 ad = pack2(a, a);
            #pragma unroll
            for (int j = 0; j < 4; ++j) acc[i2][j] = ffma2(ad, bp[j], acc[i2][j]);
        }
    }
    #pragma unroll
    for (int i2 = 0; i2 < 4; ++i2) {
        size_t row = (size_t)bt * 128 + isU * 64 + ty * 4 + i2;
        #pragma unroll
        for (int j = 0; j < 4; ++j) {
            float2 v = unpack2(acc[i2][j]);
            __nv_bfloat16 hx = __float2bfloat16(v.x), hy = __float2bfloat16(v.y);
            __nv_bfloat162 h2; h2.x = hx; h2.y = hy;
            __nv_bfloat162 l2;
            l2.x = __float2bfloat16(v.x - __bfloat162float(hx));
            l2.y = __float2bfloat16(v.y - __bfloat162float(hy));
            int n = n0 + 2 * tx + 32 * j;
            *(__nv_bfloat162*)(g_Vhi + row * N_DIM + n) = h2;
            *(__nv_bfloat162*)(g_Vlo + row * N_DIM + n) = l2;
        }
    }
}

// ---------------------------------------------------------------------------
// k_logits_tc: S-tile(128x128) = [X|emb] @ [X|emb]^T, mma.sync bf16 3-split.
// K=128 as TWO 64-k phases (phase 0 = X, phase 1 = emb) -> 66KB smem.
// __launch_bounds__(256,2): 128-reg cap => 2 CTAs/SM for pipe overlap.
// ---------------------------------------------------------------------------
#define LT_RS 65536
#define SMEM_LT (65536 + 2048)
__global__ __launch_bounds__(256, 2) void k_logits_tc() {
    extern __shared__ char smc[];
    const int cbi = blockIdx.x, rbi = blockIdx.y, bt = blockIdx.z;
    const int cb = cbi * 128, rb = rbi * 128;
    const int tid = threadIdx.x;
    const int wid = tid >> 5, lane = tid & 31;
    const uint32_t sbase = smem_u32(smc);
    const int wm = (wid & 1) * 64, wn = (wid >> 1) * 32;
    const int mat = lane >> 3, rl = lane & 7;
    const size_t xb = (size_t)bt * N_DIM * 64;
    float acc[4][4][4] = {};

    #pragma unroll
    for (int p = 0; p < 2; ++p) {
        // Load 4 tiles of 128 rows x 64 bf16 (SW128): Ah, Al, Bh, Bl
        const __nv_bfloat16* srcs[4];
        if (p == 0) {
            srcs[0] = g_Xhi + xb + (size_t)rb * 64;
            srcs[1] = g_Xlo + xb + (size_t)rb * 64;
            srcs[2] = g_Xhi + xb + (size_t)cb * 64;
            srcs[3] = g_Xlo + xb + (size_t)cb * 64;
        } else {
            srcs[0] = g_EMhi + (size_t)rb * 64;
            srcs[1] = g_EMlo + (size_t)rb * 64;
            srcs[2] = g_EMhi + (size_t)cb * 64;
            srcs[3] = g_EMlo + (size_t)cb * 64;
        }
        #pragma unroll
        for (int tile = 0; tile < 4; ++tile) {
            char* dst = smc + tile * 16384;
            const __nv_bfloat16* sp = srcs[tile];
            #pragma unroll
            for (int it = 0; it < 4; ++it) {
                int i = tid + it * 256;
                int row = i >> 3, q = i & 7;
                uint32_t off = (uint32_t)(row * 128 + q * 16);
                off ^= (off >> 3) & 0x70;
                *(uint4*)(dst + off) = *(const uint4*)(sp + (size_t)row * 64 + q * 8);
            }
        }
        __syncthreads();

        const uint32_t aH = sbase, aL = sbase + 16384;
        const uint32_t bH = sbase + 32768, bL = sbase + 49152;
        #pragma unroll
        for (int kk = 0; kk < 4; ++kk) {
            const int kb = kk * 32;
            // B fragments hoisted per k16 (16 regs live)
            uint32_t Bh[4][2], Bl[4][2];
            #pragma unroll
            for (int g = 0; g < 2; ++g) {
                int nrow = wn + g * 16 + (mat >> 1) * 8 + rl;
                int col = kb + (mat & 1) * 16;
                uint32_t th[4], tl[4];
                ldm4(swadr(bH, nrow, col), th);
                ldm4(swadr(bL, nrow, col), tl);
                Bh[2 * g][0] = th[0]; Bh[2 * g][1] = th[1];
                Bh[2 * g + 1][0] = th[2]; Bh[2 * g + 1][1] = th[3];
                Bl[2 * g][0] = tl[0]; Bl[2 * g][1] = tl[1];
                Bl[2 * g + 1][0] = tl[2]; Bl[2 * g + 1][1] = tl[3];
            }
            // A per mi: load 8 regs, fire 12 MMAs, release
            #pragma unroll
            for (int mi = 0; mi < 4; ++mi) {
                int row = wm + mi * 16 + (mat & 1) * 8 + rl;
                int col = kb + (mat >> 1) * 16;
                uint32_t Ah[4], Al[4];
                ldm4(swadr(aH, row, col), Ah);
                ldm4(swadr(aL, row, col), Al);
                #pragma unroll
                for (int ni = 0; ni < 4; ++ni) {
                    mma16816(acc[mi][ni], Ah, Bh[ni]);
                    mma16816(acc[mi][ni], Ah, Bl[ni]);
                    mma16816(acc[mi][ni], Al, Bh[ni]);
                }
            }
        }
        __syncthreads();
    }

    // Epilogue: relu, exp(-D), split-store, deterministic row-sum partials
    float* rs = (float*)(smc + LT_RS);  // [4 warp_n][128 rows]
    #pragma unroll
    for (int mi = 0; mi < 4; ++mi) {
        #pragma unroll
        for (int h = 0; h < 2; ++h) {
            int rloc = wm + mi * 16 + h * 8 + (lane >> 2);
            int r = rb + rloc;
            float dr = g_D[(size_t)bt * N_DIM + r];
            __nv_bfloat16* sh = g_Shi + ((size_t)bt * N_DIM + r) * N_DIM + cb + wn;
            __nv_bfloat16* sl = g_Slo + ((size_t)bt * N_DIM + r) * N_DIM + cb + wn;
            float rsum = 0.0f;
            #pragma unroll
            for (int ni = 0; ni < 4; ++ni) {
                float p0 = __expf(fmaxf(acc[mi][ni][h * 2 + 0], 0.0f) - dr);
                float p1 = __expf(fmaxf(acc[mi][ni][h * 2 + 1], 0.0f) - dr);
                rsum += p0 + p1;
                __nv_bfloat162 hh, ll;
                hh.x = __float2bfloat16(p0);
                hh.y = __float2bfloat16(p1);
                ll.x = __float2bfloat16(p0 - __bfloat162float(hh.x));
                ll.y = __float2bfloat16(p1 - __bfloat162float(hh.y));
                int c = ni * 8 + (lane & 3) * 2;
                *(__nv_bfloat162*)(sh + c) = hh;
                *(__nv_bfloat162*)(sl + c) = ll;
            }
            rsum += __shfl_xor_sync(0xffffffffu, rsum, 1);
            rsum += __shfl_xor_sync(0xffffffffu, rsum, 2);
            if ((lane & 3) == 0) rs[(wid >> 1) * 128 + rloc] = rsum;
        }
    }
    __syncthreads();
    if (tid < 128) {
        float tot = rs[tid] + rs[128 + tid] + rs[256 + tid] + rs[384 + tid];
        g_RSP[((size_t)bt * 4 + cbi) * N_DIM + rb + tid] = tot;
    }
}

// ---------------------------------------------------------------------------
// k_out_tc: OUT-tile(128 rows x 128 ch) = relu(inv_rs * (E @ Vt^T));
// K=512 in 8 chunks, mma.sync bf16 3-split, 128-reg cap => 2 CTAs/SM.
// ---------------------------------------------------------------------------
#define SMEM_OT 65536
__global__ __launch_bounds__(256, 2) void k_out_tc(float* __restrict__ out, size_t uf_off) {
    extern __shared__ char smc[];
    const int rbi = blockIdx.x, bt = blockIdx.y;
    const int rb = rbi * 128;
    const int b = bt / T_DIM, t = bt % T_DIM;
    const int tid = threadIdx.x;
    const int wid = tid >> 5, lane = tid & 31;
    const uint32_t sbase = smem_u32(smc);
    const int wm = (wid & 1) * 64, wn = (wid >> 1) * 32;
    const int mat = lane >> 3, rl = lane & 7;
    float acc[4][4][4] = {};

    for (int kt = 0; kt < 8; ++kt) {
        const __nv_bfloat16* srcs[4] = {
            g_Shi + ((size_t)bt * N_DIM + rb) * N_DIM + kt * 64,
            g_Slo + ((size_t)bt * N_DIM + rb) * N_DIM + kt * 64,
            g_Vhi + ((size_t)bt * 128) * N_DIM + kt * 64,
            g_Vlo + ((size_t)bt * 128) * N_DIM + kt * 64,
        };
        #pragma unroll
        for (int tile = 0; tile < 4; ++tile) {
            char* dst = smc + tile * 16384;
            const __nv_bfloat16* sp = srcs[tile];
            #pragma unroll
            for (int it = 0; it < 4; ++it) {
                int i = tid + it * 256;
                int row = i >> 3, q = i & 7;
                uint32_t off = (uint32_t)(row * 128 + q * 16);
                off ^= (off >> 3) & 0x70;
                *(uint4*)(dst + off) = *(const uint4*)(sp + (size_t)row * N_DIM + q * 8);
            }
        }
        __syncthreads();

        const uint32_t aH = sbase, aL = sbase + 16384;
        const uint32_t bH = sbase + 32768, bL = sbase + 49152;
        #pragma unroll
        for (int kk = 0; kk < 4; ++kk) {
            const int kb = kk * 32;
            uint32_t Bh[4][2], Bl[4][2];
            #pragma unroll
            for (int g = 0; g < 2; ++g) {
                int nrow = wn + g * 16 + (mat >> 1) * 8 + rl;
                int col = kb + (mat & 1) * 16;
                uint32_t th[4], tl[4];
                ldm4(swadr(bH, nrow, col), th);
                ldm4(swadr(bL, nrow, col), tl);
                Bh[2 * g][0] = th[0]; Bh[2 * g][1] = th[1];
                Bh[2 * g + 1][0] = th[2]; Bh[2 * g + 1][1] = th[3];
                Bl[2 * g][0] = tl[0]; Bl[2 * g][1] = tl[1];
                Bl[2 * g + 1][0] = tl[2]; Bl[2 * g + 1][1] = tl[3];
            }
            #pragma unroll
            for (int mi = 0; mi < 4; ++mi) {
                int row = wm + mi * 16 + (mat & 1) * 8 + rl;
                int col = kb + (mat >> 1) * 16;
                uint32_t Ah[4], Al[4];
                ldm4(swadr(aH, row, col), Ah);
                ldm4(swadr(aL, row, col), Al);
                #pragma unroll
                for (int ni = 0; ni < 4; ++ni) {
                    mma16816(acc[mi][ni], Ah, Bh[ni]);
                    mma16816(acc[mi][ni], Ah, Bl[ni]);
                    mma16816(acc[mi][ni], Al, Bh[ni]);
                }
            }
        }
        __syncthreads();
    }

    // Epilogue: normalize by row sum, relu, scatter to (B,N,T,F) of/uf
    #pragma unroll
    for (int mi = 0; mi < 4; ++mi) {
        #pragma unroll
        for (int h = 0; h < 2; ++h) {
            int n = rb + wm + mi * 16 + h * 8 + (lane >> 2);
            size_t rsb = (size_t)bt * 4 * N_DIM + n;
            float rsv = g_RSP[rsb] + g_RSP[rsb + N_DIM] +
                        g_RSP[rsb + 2 * N_DIM] + g_RSP[rsb + 3 * N_DIM];
            float inv = 1.0f / rsv;
            size_t obase = (size_t)b * 786432 + (size_t)n * 1536 + (size_t)t * 64;
            #pragma unroll
            for (int ni = 0; ni < 4; ++ni) {
                int ch = wn + ni * 8 + (lane & 3) * 2;
                float2 v;
                v.x = fmaxf(acc[mi][ni][h * 2 + 0] * inv, 0.0f);
                v.y = fmaxf(acc[mi][ni][h * 2 + 1] * inv, 0.0f);
                if (ch < 64) *(float2*)(out + obase + ch) = v;
                else         *(float2*)(out + uf_off + obase + (ch - 64)) = v;
            }
        }
    }
}

// ---------------------------------------------------------------------------
extern "C" void kernel_launch(void* const* d_in, const int* in_sizes, int n_in,
                              void* d_out, int out_size) {
    const float* ori = (const float*)d_in[0];   // (16,512,24,64)
    const float* unc = (const float*)d_in[1];   // (16,512,24,64)
    const float* emb = (const float*)d_in[2];   // (512,64)
    const float* W1  = (const float*)d_in[3];   // (64,64)
    float* out = (float*)d_out;                 // [of | uf]
    const size_t uf_off = (size_t)out_size / 2;

    const int SMEM_VWT = (64 * 66 + 64 * VWP) * 4;  // 50176 B
    cudaFuncSetAttribute(k_vwt, cudaFuncAttributeMaxDynamicSharedMemorySize, SMEM_VWT);
    cudaFuncSetAttribute(k_logits_tc, cudaFuncAttributeMaxDynamicSharedMemorySize, SMEM_LT);
    cudaFuncSetAttribute(k_out_tc, cudaFuncAttributeMaxDynamicSharedMemorySize, SMEM_OT);

    k_embprep<<<8, 256>>>(emb);
    k_prep<<<dim3(8, BT_DIM), 256>>>(ori);
    k_vwt<<<dim3(8, BT_DIM), 256, SMEM_VWT>>>(ori, unc, W1);
    k_logits_tc<<<dim3(4, 4, BT_DIM), 256, SMEM_LT>>>();
    k_out_tc<<<dim3(4, BT_DIM), 256, SMEM_OT>>>(out, uf_off);
}

// round 13
// speedup vs baseline: 1.9189x; 1.0846x over previous
#include <cuda_runtime.h>
#include <cuda_bf16.h>
#include <cstddef>
#include <cstdint>

// B=16, N=512, T=24, F=64, BT=384
#define T_DIM 24
#define N_DIM 512
#define BT_DIM 384

// Scratch (device globals: allocation-free per harness rules)
static __device__ float g_D[(size_t)BT_DIM * N_DIM];                         // diag shift
static __device__ float g_ED[N_DIM];                                         // ||emb_n||^2
static __device__ __nv_bfloat16 g_EMhi[N_DIM * 64];                          // emb hi
static __device__ __nv_bfloat16 g_EMlo[N_DIM * 64];                          // emb lo
static __device__ __nv_bfloat16 g_Xhi[(size_t)BT_DIM * N_DIM * 64];          // 25 MB
static __device__ __nv_bfloat16 g_Xlo[(size_t)BT_DIM * N_DIM * 64];          // 25 MB
static __device__ __nv_bfloat16 g_Vhi[(size_t)BT_DIM * 128 * N_DIM];         // 50 MB
static __device__ __nv_bfloat16 g_Vlo[(size_t)BT_DIM * 128 * N_DIM];         // 50 MB

typedef unsigned long long u64;
__device__ __forceinline__ u64 pack2(float lo, float hi) {
    u64 r; asm("mov.b64 %0, {%1, %2};" : "=l"(r) : "f"(lo), "f"(hi)); return r;
}
__device__ __forceinline__ u64 ffma2(u64 a, u64 b, u64 c) {
    u64 d; asm("fma.rn.f32x2 %0, %1, %2, %3;" : "=l"(d) : "l"(a), "l"(b), "l"(c)); return d;
}
__device__ __forceinline__ float2 unpack2(u64 v) {
    float2 r; asm("mov.b64 {%0, %1}, %2;" : "=f"(r.x), "=f"(r.y) : "l"(v)); return r;
}

// ---- warp-level tensor core plumbing (sm_80 baseline PTX) ------------------
__device__ __forceinline__ uint32_t smem_u32(const void* p) {
    uint32_t a;
    asm("{ .reg .u64 t; cvta.to.shared.u64 t, %1; cvt.u32.u64 %0, t; }" : "=r"(a) : "l"(p));
    return a;
}
__device__ __forceinline__ void ldm4(uint32_t addr, uint32_t* r) {
    asm volatile("ldmatrix.sync.aligned.m8n8.x4.shared.b16 {%0,%1,%2,%3}, [%4];"
                 : "=r"(r[0]), "=r"(r[1]), "=r"(r[2]), "=r"(r[3]) : "r"(addr));
}
__device__ __forceinline__ void mma16816(float* d, const uint32_t* a, const uint32_t* b) {
    asm volatile("mma.sync.aligned.m16n8k16.row.col.f32.bf16.bf16.f32 "
        "{%0,%1,%2,%3}, {%4,%5,%6,%7}, {%8,%9}, {%0,%1,%2,%3};"
        : "+f"(d[0]), "+f"(d[1]), "+f"(d[2]), "+f"(d[3])
        : "r"(a[0]), "r"(a[1]), "r"(a[2]), "r"(a[3]), "r"(b[0]), "r"(b[1]));
}
// SW128 swizzle for 128B-pitch tiles
__device__ __forceinline__ uint32_t swadr(uint32_t base, int row, int colb) {
    uint32_t off = row * 128 + colb;
    return base + (off ^ ((off >> 3) & 0x70));
}

// ---------------------------------------------------------------------------
// k_embprep: emb -> bf16 hi/lo, g_ED[n] = ||emb_n||^2
// ---------------------------------------------------------------------------
__global__ void k_embprep(const float* __restrict__ emb) {
    const int tid = threadIdx.x;
    const int rl = tid >> 2, q = tid & 3;
    const int n = blockIdx.x * 64 + rl;
    const float* src = emb + n * 64 + q * 16;
    float ss = 0.0f;
    __align__(16) __nv_bfloat16 hb[16], lb[16];
    #pragma unroll
    for (int i = 0; i < 4; ++i) {
        float4 v = ((const float4*)src)[i];
        float vv[4] = {v.x, v.y, v.z, v.w};
        #pragma unroll
        for (int j = 0; j < 4; ++j) {
            ss += vv[j] * vv[j];
            __nv_bfloat16 h = __float2bfloat16(vv[j]);
            hb[i * 4 + j] = h;
            lb[i * 4 + j] = __float2bfloat16(vv[j] - __bfloat162float(h));
        }
    }
    size_t xo = (size_t)n * 64 + q * 16;
    ((uint4*)(g_EMhi + xo))[0] = ((uint4*)hb)[0];
    ((uint4*)(g_EMhi + xo))[1] = ((uint4*)hb)[1];
    ((uint4*)(g_EMlo + xo))[0] = ((uint4*)lb)[0];
    ((uint4*)(g_EMlo + xo))[1] = ((uint4*)lb)[1];
    ss += __shfl_xor_sync(0xffffffffu, ss, 1);
    ss += __shfl_xor_sync(0xffffffffu, ss, 2);
    if (q == 0) g_ED[n] = ss;
}

// ---------------------------------------------------------------------------
// k_prep: X -> bf16 hi/lo (per-bt layout), D[bt][n] = ||x||^2 + ||emb_n||^2
// ---------------------------------------------------------------------------
__global__ void k_prep(const float* __restrict__ ori) {
    const int bt = blockIdx.y, b = bt / T_DIM, t = bt % T_DIM;
    const int tid = threadIdx.x;
    const int rl = tid >> 2, q = tid & 3;
    const int n = blockIdx.x * 64 + rl;
    const float* src = ori + (size_t)b * 786432 + (size_t)n * 1536 + (size_t)t * 64 + q * 16;
    float ss = 0.0f;
    __align__(16) __nv_bfloat16 hb[16], lb[16];
    #pragma unroll
    for (int i = 0; i < 4; ++i) {
        float4 v = ((const float4*)src)[i];
        float vv[4] = {v.x, v.y, v.z, v.w};
        #pragma unroll
        for (int j = 0; j < 4; ++j) {
            ss += vv[j] * vv[j];
            __nv_bfloat16 h = __float2bfloat16(vv[j]);
            hb[i * 4 + j] = h;
            lb[i * 4 + j] = __float2bfloat16(vv[j] - __bfloat162float(h));
        }
    }
    size_t xo = ((size_t)bt * N_DIM + n) * 64 + q * 16;
    ((uint4*)(g_Xhi + xo))[0] = ((uint4*)hb)[0];
    ((uint4*)(g_Xhi + xo))[1] = ((uint4*)hb)[1];
    ((uint4*)(g_Xlo + xo))[0] = ((uint4*)lb)[0];
    ((uint4*)(g_Xlo + xo))[1] = ((uint4*)lb)[1];
    ss += __shfl_xor_sync(0xffffffffu, ss, 1);
    ss += __shfl_xor_sync(0xffffffffu, ss, 2);
    if (q == 0)
        g_D[(size_t)bt * N_DIM + n] = ss + g_ED[n];
}

// ---------------------------------------------------------------------------
// k_vwt: Vt[bt][c][n] = (W1 @ srcT); c<64 from X, c>=64 from U; bf16 hi/lo out.
// ---------------------------------------------------------------------------
#define VWP 130
__global__ __launch_bounds__(256, 2) void k_vwt(const float* __restrict__ ori,
                                                const float* __restrict__ unc,
                                                const float* __restrict__ W1) {
    extern __shared__ float sm[];
    float (*Ws)[66]  = (float(*)[66])sm;              // (f, c) 64x66
    float (*Bs)[VWP] = (float(*)[VWP])(sm + 64 * 66); // (f, n) 64x130
    const int sx = blockIdx.x, bt = blockIdx.y;
    const int isU = sx >> 2, nc = sx & 3;
    const int n0 = nc * 128;
    const int b = bt / T_DIM, t = bt % T_DIM;
    const int tid = threadIdx.x;
    const float* src = isU ? unc : ori;
    const size_t base = (size_t)b * 786432 + (size_t)t * 64;

    #pragma unroll
    for (int it = 0; it < 4; ++it) {
        int i = tid + it * 256;
        int o = i >> 4, q = i & 15;
        float4 w = *(const float4*)(W1 + o * 64 + q * 4);
        Ws[q * 4 + 0][o] = w.x; Ws[q * 4 + 1][o] = w.y;
        Ws[q * 4 + 2][o] = w.z; Ws[q * 4 + 3][o] = w.w;
    }
    #pragma unroll
    for (int it = 0; it < 8; ++it) {
        int i = tid + it * 256;
        int r = i >> 4, q = i & 15;
        float4 v = *(const float4*)(src + base + (size_t)(n0 + r) * 1536 + q * 4);
        Bs[q * 4 + 0][r] = v.x; Bs[q * 4 + 1][r] = v.y;
        Bs[q * 4 + 2][r] = v.z; Bs[q * 4 + 3][r] = v.w;
    }
    __syncthreads();

    const int ty = tid >> 4, tx = tid & 15;
    u64 acc[4][4] = {};
    #pragma unroll 8
    for (int k = 0; k < 64; ++k) {
        u64 bp[4];
        #pragma unroll
        for (int j = 0; j < 4; ++j) bp[j] = *(const u64*)(&Bs[k][2 * tx + 32 * j]);
        #pragma unroll
        for (int i2 = 0; i2 < 4; ++i2) {
            float a = Ws[k][ty * 4 + i2];
            u64 ad = pack2(a, a);
            #pragma unroll
            for (int j = 0; j < 4; ++j) acc[i2][j] = ffma2(ad, bp[j], acc[i2][j]);
        }
    }
    #pragma unroll
    for (int i2 = 0; i2 < 4; ++i2) {
        size_t row = (size_t)bt * 128 + isU * 64 + ty * 4 + i2;
        #pragma unroll
        for (int j = 0; j < 4; ++j) {
            float2 v = unpack2(acc[i2][j]);
            __nv_bfloat16 hx = __float2bfloat16(v.x), hy = __float2bfloat16(v.y);
            __nv_bfloat162 h2; h2.x = hx; h2.y = hy;
            __nv_bfloat162 l2;
            l2.x = __float2bfloat16(v.x - __bfloat162float(hx));
            l2.y = __float2bfloat16(v.y - __bfloat162float(hy));
            int n = n0 + 2 * tx + 32 * j;
            *(__nv_bfloat162*)(g_Vhi + row * N_DIM + n) = h2;
            *(__nv_bfloat162*)(g_Vlo + row * N_DIM + n) = l2;
        }
    }
}

// ---------------------------------------------------------------------------
// k_fused: per (bt, 128-row block): for each 128-col chunk:
//   GEMM1 (3-split, K=128 in X/emb phases) -> exp(relu-D) in regs ->
//   P(bf16 hi/lo) to smem -> GEMM2 (P @ V chunk, 3-split) accumulating OUT.
// Final: OUT * (1/rowsum), relu, scatter. No S in gmem at all.
// smem: A 64K | Bstream 32K | P 64K | V 64K = 224KB.
// ---------------------------------------------------------------------------
#define SA_XHI 0
#define SA_XLO 16384
#define SA_EHI 32768
#define SA_ELO 49152
#define SB_HI  65536
#define SB_LO  81920
#define SP_HI  98304
#define SP_LO  131072
#define SV_HI  163840
#define SV_LO  196608
#define SMEM_FU 229376

__device__ __forceinline__ void load_tile(char* dst, const __nv_bfloat16* sp,
                                          int stride, int tid) {
    #pragma unroll
    for (int it = 0; it < 4; ++it) {
        int i = tid + it * 256;
        int row = i >> 3, q = i & 7;
        uint32_t off = (uint32_t)(row * 128 + q * 16);
        off ^= (off >> 3) & 0x70;
        *(uint4*)(dst + off) = *(const uint4*)(sp + (size_t)row * stride + q * 8);
    }
}

__global__ __launch_bounds__(256) void k_fused(float* __restrict__ out, size_t uf_off) {
    extern __shared__ char smc[];
    const int rbi = blockIdx.x, bt = blockIdx.y;
    const int rb = rbi * 128;
    const int b = bt / T_DIM, t = bt % T_DIM;
    const int tid = threadIdx.x;
    const int wid = tid >> 5, lane = tid & 31;
    const uint32_t sbase = smem_u32(smc);
    const int wm = (wid & 1) * 64, wn = (wid >> 1) * 32;
    const int mat = lane >> 3, rl = lane & 7;
    const size_t xb = (size_t)bt * N_DIM * 64;

    // Persistent A tiles: X[rb] hi/lo, EM[rb] hi/lo
    load_tile(smc + SA_XHI, g_Xhi + xb + (size_t)rb * 64, 64, tid);
    load_tile(smc + SA_XLO, g_Xlo + xb + (size_t)rb * 64, 64, tid);
    load_tile(smc + SA_EHI, g_EMhi + (size_t)rb * 64, 64, tid);
    load_tile(smc + SA_ELO, g_EMlo + (size_t)rb * 64, 64, tid);

    float accO[4][4][4] = {};
    float rsum[4][2] = {};

    for (int cbi = 0; cbi < 4; ++cbi) {
        const int cb = cbi * 128;
        // V tiles for this chunk (2 k-halves, hi/lo)
        const __nv_bfloat16* vh = g_Vhi + (size_t)bt * 128 * N_DIM + cb;
        const __nv_bfloat16* vl = g_Vlo + (size_t)bt * 128 * N_DIM + cb;
        load_tile(smc + SV_HI,         vh,      N_DIM, tid);
        load_tile(smc + SV_HI + 16384, vh + 64, N_DIM, tid);
        load_tile(smc + SV_LO,         vl,      N_DIM, tid);
        load_tile(smc + SV_LO + 16384, vl + 64, N_DIM, tid);
        // B phase 0: X[cb]
        load_tile(smc + SB_HI, g_Xhi + xb + (size_t)cb * 64, 64, tid);
        load_tile(smc + SB_LO, g_Xlo + xb + (size_t)cb * 64, 64, tid);
        __syncthreads();

        float accE[4][4][4] = {};
        // ---- GEMM1, two phases of K=64 ----
        #pragma unroll
        for (int p = 0; p < 2; ++p) {
            const uint32_t aH = sbase + (p ? SA_EHI : SA_XHI);
            const uint32_t aL = sbase + (p ? SA_ELO : SA_XLO);
            const uint32_t bH = sbase + SB_HI, bL = sbase + SB_LO;
            #pragma unroll
            for (int kk = 0; kk < 4; ++kk) {
                const int kb = kk * 32;
                uint32_t Bh[4][2], Bl[4][2];
                #pragma unroll
                for (int g = 0; g < 2; ++g) {
                    int nrow = wn + g * 16 + (mat >> 1) * 8 + rl;
                    int col = kb + (mat & 1) * 16;
                    uint32_t th[4], tl[4];
                    ldm4(swadr(bH, nrow, col), th);
                    ldm4(swadr(bL, nrow, col), tl);
                    Bh[2 * g][0] = th[0]; Bh[2 * g][1] = th[1];
                    Bh[2 * g + 1][0] = th[2]; Bh[2 * g + 1][1] = th[3];
                    Bl[2 * g][0] = tl[0]; Bl[2 * g][1] = tl[1];
                    Bl[2 * g + 1][0] = tl[2]; Bl[2 * g + 1][1] = tl[3];
                }
                #pragma unroll
                for (int mi = 0; mi < 4; ++mi) {
                    int row = wm + mi * 16 + (mat & 1) * 8 + rl;
                    int col = kb + (mat >> 1) * 16;
                    uint32_t Ah[4], Al[4];
                    ldm4(swadr(aH, row, col), Ah);
                    ldm4(swadr(aL, row, col), Al);
                    #pragma unroll
                    for (int ni = 0; ni < 4; ++ni) {
                        mma16816(accE[mi][ni], Ah, Bh[ni]);
                        mma16816(accE[mi][ni], Ah, Bl[ni]);
                        mma16816(accE[mi][ni], Al, Bh[ni]);
                    }
                }
            }
            if (p == 0) {
                // swap B to EM[cb]
                __syncthreads();
                load_tile(smc + SB_HI, g_EMhi + (size_t)cb * 64, 64, tid);
                load_tile(smc + SB_LO, g_EMlo + (size_t)cb * 64, 64, tid);
                __syncthreads();
            }
        }

        // ---- epilogue: exp(relu - D), rowsum, pack P hi/lo into smem ----
        #pragma unroll
        for (int mi = 0; mi < 4; ++mi) {
            #pragma unroll
            for (int h = 0; h < 2; ++h) {
                int rloc = wm + mi * 16 + h * 8 + (lane >> 2);
                float dr = g_D[(size_t)bt * N_DIM + rb + rloc];
                #pragma unroll
                for (int ni = 0; ni < 4; ++ni) {
                    float p0 = __expf(fmaxf(accE[mi][ni][h * 2 + 0], 0.0f) - dr);
                    float p1 = __expf(fmaxf(accE[mi][ni][h * 2 + 1], 0.0f) - dr);
                    rsum[mi][h] += p0 + p1;
                    __nv_bfloat162 hh, ll;
                    hh.x = __float2bfloat16(p0);
                    hh.y = __float2bfloat16(p1);
                    ll.x = __float2bfloat16(p0 - __bfloat162float(hh.x));
                    ll.y = __float2bfloat16(p1 - __bfloat162float(hh.y));
                    int n = wn + ni * 8 + (lane & 3) * 2;
                    int tn = n >> 6, nc2 = n & 63;
                    uint32_t off = (uint32_t)(rloc * 128 + nc2 * 2);
                    off ^= (off >> 3) & 0x70;
                    *(__nv_bfloat162*)(smc + SP_HI + tn * 16384 + off) = hh;
                    *(__nv_bfloat162*)(smc + SP_LO + tn * 16384 + off) = ll;
                }
            }
        }
        __syncthreads();

        // ---- GEMM2: OUT += P @ V^T (K = 128 chunk cols, 8 k16 tiles) ----
        #pragma unroll
        for (int kk2 = 0; kk2 < 8; ++kk2) {
            const int tile = kk2 >> 2, kb = (kk2 & 3) * 32;
            const uint32_t aH = sbase + SP_HI + tile * 16384;
            const uint32_t aL = sbase + SP_LO + tile * 16384;
            const uint32_t bH = sbase + SV_HI + tile * 16384;
            const uint32_t bL = sbase + SV_LO + tile * 16384;
            uint32_t Bh[4][2], Bl[4][2];
            #pragma unroll
            for (int g = 0; g < 2; ++g) {
                int nrow = wn + g * 16 + (mat >> 1) * 8 + rl;
                int col = kb + (mat & 1) * 16;
                uint32_t th[4], tl[4];
                ldm4(swadr(bH, nrow, col), th);
                ldm4(swadr(bL, nrow, col), tl);
                Bh[2 * g][0] = th[0]; Bh[2 * g][1] = th[1];
                Bh[2 * g + 1][0] = th[2]; Bh[2 * g + 1][1] = th[3];
                Bl[2 * g][0] = tl[0]; Bl[2 * g][1] = tl[1];
                Bl[2 * g + 1][0] = tl[2]; Bl[2 * g + 1][1] = tl[3];
            }
            #pragma unroll
            for (int mi = 0; mi < 4; ++mi) {
                int row = wm + mi * 16 + (mat & 1) * 8 + rl;
                int col = kb + (mat >> 1) * 16;
                uint32_t Ah[4], Al[4];
                ldm4(swadr(aH, row, col), Ah);
                ldm4(swadr(aL, row, col), Al);
                #pragma unroll
                for (int ni = 0; ni < 4; ++ni) {
                    mma16816(accO[mi][ni], Ah, Bh[ni]);
                    mma16816(accO[mi][ni], Ah, Bl[ni]);
                    mma16816(accO[mi][ni], Al, Bh[ni]);
                }
            }
        }
        __syncthreads();
    }

    // ---- rowsum cross-warp reduce (reuse B-stream region) ----
    float* rs = (float*)(smc + SB_HI);  // [4 wn-groups][128 rows]
    #pragma unroll
    for (int mi = 0; mi < 4; ++mi) {
        #pragma unroll
        for (int h = 0; h < 2; ++h) {
            float v = rsum[mi][h];
            v += __shfl_xor_sync(0xffffffffu, v, 1);
            v += __shfl_xor_sync(0xffffffffu, v, 2);
            if ((lane & 3) == 0) {
                int rloc = wm + mi * 16 + h * 8 + (lane >> 2);
                rs[(wid >> 1) * 128 + rloc] = v;
            }
        }
    }
    __syncthreads();

    // ---- final: normalize, relu, scatter ----
    #pragma unroll
    for (int mi = 0; mi < 4; ++mi) {
        #pragma unroll
        for (int h = 0; h < 2; ++h) {
            int rloc = wm + mi * 16 + h * 8 + (lane >> 2);
            int n = rb + rloc;
            float tot = rs[rloc] + rs[128 + rloc] + rs[256 + rloc] + rs[384 + rloc];
            float inv = 1.0f / tot;
            size_t obase = (size_t)b * 786432 + (size_t)n * 1536 + (size_t)t * 64;
            #pragma unroll
            for (int ni = 0; ni < 4; ++ni) {
                int ch = wn + ni * 8 + (lane & 3) * 2;
                float2 v;
                v.x = fmaxf(accO[mi][ni][h * 2 + 0] * inv, 0.0f);
                v.y = fmaxf(accO[mi][ni][h * 2 + 1] * inv, 0.0f);
                if (ch < 64) *(float2*)(out + obase + ch) = v;
                else         *(float2*)(out + uf_off + obase + (ch - 64)) = v;
            }
        }
    }
}

// ---------------------------------------------------------------------------
extern "C" void kernel_launch(void* const* d_in, const int* in_sizes, int n_in,
                              void* d_out, int out_size) {
    const float* ori = (const float*)d_in[0];   // (16,512,24,64)
    const float* unc = (const float*)d_in[1];   // (16,512,24,64)
    const float* emb = (const float*)d_in[2];   // (512,64)
    const float* W1  = (const float*)d_in[3];   // (64,64)
    float* out = (float*)d_out;                 // [of | uf]
    const size_t uf_off = (size_t)out_size / 2;

    const int SMEM_VWT = (64 * 66 + 64 * VWP) * 4;  // 50176 B
    cudaFuncSetAttribute(k_vwt, cudaFuncAttributeMaxDynamicSharedMemorySize, SMEM_VWT);
    cudaFuncSetAttribute(k_fused, cudaFuncAttributeMaxDynamicSharedMemorySize, SMEM_FU);

    k_embprep<<<8, 256>>>(emb);
    k_prep<<<dim3(8, BT_DIM), 256>>>(ori);
    k_vwt<<<dim3(8, BT_DIM), 256, SMEM_VWT>>>(ori, unc, W1);
    k_fused<<<dim3(4, BT_DIM), 256, SMEM_FU>>>(out, uf_off);
}

// round 14
// speedup vs baseline: 2.3902x; 1.2456x over previous
#include <cuda_runtime.h>
#include <cuda_bf16.h>
#include <cstddef>
#include <cstdint>

// B=16, N=512, T=24, F=64, BT=384
#define T_DIM 24
#define N_DIM 512
#define BT_DIM 384

// Scratch (device globals: allocation-free per harness rules)
static __device__ float g_EE[N_DIM * N_DIM];                                 // 1 MB, emb@emb^T
static __device__ float g_ED[N_DIM];                                         // ||emb_n||^2
static __device__ float g_D[(size_t)BT_DIM * N_DIM];                         // diag shift
static __device__ __nv_bfloat16 g_Xhi[(size_t)BT_DIM * N_DIM * 64];          // 25 MB
static __device__ __nv_bfloat16 g_Xlo[(size_t)BT_DIM * N_DIM * 64];          // 25 MB
static __device__ __nv_bfloat16 g_Vhi[(size_t)BT_DIM * 128 * N_DIM];         // 50 MB
static __device__ __nv_bfloat16 g_Vlo[(size_t)BT_DIM * 128 * N_DIM];         // 50 MB

typedef unsigned long long u64;
__device__ __forceinline__ u64 pack2(float lo, float hi) {
    u64 r; asm("mov.b64 %0, {%1, %2};" : "=l"(r) : "f"(lo), "f"(hi)); return r;
}
__device__ __forceinline__ u64 ffma2(u64 a, u64 b, u64 c) {
    u64 d; asm("fma.rn.f32x2 %0, %1, %2, %3;" : "=l"(d) : "l"(a), "l"(b), "l"(c)); return d;
}
__device__ __forceinline__ float2 unpack2(u64 v) {
    float2 r; asm("mov.b64 {%0, %1}, %2;" : "=f"(r.x), "=f"(r.y) : "l"(v)); return r;
}

// ---- warp-level tensor core plumbing (sm_80 baseline PTX) ------------------
__device__ __forceinline__ uint32_t smem_u32(const void* p) {
    uint32_t a;
    asm("{ .reg .u64 t; cvta.to.shared.u64 t, %1; cvt.u32.u64 %0, t; }" : "=r"(a) : "l"(p));
    return a;
}
__device__ __forceinline__ void ldm4(uint32_t addr, uint32_t* r) {
    asm volatile("ldmatrix.sync.aligned.m8n8.x4.shared.b16 {%0,%1,%2,%3}, [%4];"
                 : "=r"(r[0]), "=r"(r[1]), "=r"(r[2]), "=r"(r[3]) : "r"(addr));
}
__device__ __forceinline__ void mma16816(float* d, const uint32_t* a, const uint32_t* b) {
    asm volatile("mma.sync.aligned.m16n8k16.row.col.f32.bf16.bf16.f32 "
        "{%0,%1,%2,%3}, {%4,%5,%6,%7}, {%8,%9}, {%0,%1,%2,%3};"
        : "+f"(d[0]), "+f"(d[1]), "+f"(d[2]), "+f"(d[3])
        : "r"(a[0]), "r"(a[1]), "r"(a[2]), "r"(a[3]), "r"(b[0]), "r"(b[1]));
}
// SW128 swizzle for 128B-pitch tiles
__device__ __forceinline__ uint32_t swadr(uint32_t base, int row, int colb) {
    uint32_t off = row * 128 + colb;
    return base + (off ^ ((off >> 3) & 0x70));
}
#define CP_COMMIT() asm volatile("cp.async.commit_group;" ::: "memory")
template <int N>
__device__ __forceinline__ void cp_wait() {
    asm volatile("cp.async.wait_group %0;" :: "n"(N) : "memory");
}

// ---------------------------------------------------------------------------
// k_ee: EE = emb @ emb^T (512x512, K=64) in fp32; diag -> g_ED.
// ---------------------------------------------------------------------------
__global__ void k_ee(const float* __restrict__ emb) {
    __shared__ float As[64][68];
    __shared__ float Bs[64][65];
    const int rb = blockIdx.y * 64, cb = blockIdx.x * 64;
    const int tid = threadIdx.x;
    #pragma unroll
    for (int it = 0; it < 4; ++it) {
        int i = tid + it * 256;
        int r = i >> 4, k4 = i & 15;
        float4 a = *(const float4*)(emb + (rb + r) * 64 + k4 * 4);
        *(float4*)(&As[r][k4 * 4]) = a;
        float4 w = *(const float4*)(emb + (cb + r) * 64 + k4 * 4);
        Bs[k4 * 4 + 0][r] = w.x; Bs[k4 * 4 + 1][r] = w.y;
        Bs[k4 * 4 + 2][r] = w.z; Bs[k4 * 4 + 3][r] = w.w;
    }
    __syncthreads();
    const int ty = tid >> 4, tx = tid & 15;
    float acc[4][4] = {};
    #pragma unroll 8
    for (int k = 0; k < 64; ++k) {
        float a[4], b[4];
        #pragma unroll
        for (int i = 0; i < 4; ++i) a[i] = As[ty * 4 + i][k];
        #pragma unroll
        for (int j = 0; j < 4; ++j) b[j] = Bs[k][tx + 16 * j];
        #pragma unroll
        for (int i = 0; i < 4; ++i)
            #pragma unroll
            for (int j = 0; j < 4; ++j) acc[i][j] = fmaf(a[i], b[j], acc[i][j]);
    }
    #pragma unroll
    for (int i = 0; i < 4; ++i)
        #pragma unroll
        for (int j = 0; j < 4; ++j) {
            int r = rb + ty * 4 + i, c = cb + tx + 16 * j;
            g_EE[r * N_DIM + c] = acc[i][j];
            if (r == c) g_ED[r] = acc[i][j];
        }
}

// ---------------------------------------------------------------------------
// k_prep: X -> bf16 hi/lo (per-bt layout), D[bt][n] = ||x||^2 + ||emb_n||^2
// ---------------------------------------------------------------------------
__global__ void k_prep(const float* __restrict__ ori) {
    const int bt = blockIdx.y, b = bt / T_DIM, t = bt % T_DIM;
    const int tid = threadIdx.x;
    const int rl = tid >> 2, q = tid & 3;
    const int n = blockIdx.x * 64 + rl;
    const float* src = ori + (size_t)b * 786432 + (size_t)n * 1536 + (size_t)t * 64 + q * 16;
    float ss = 0.0f;
    __align__(16) __nv_bfloat16 hb[16], lb[16];
    #pragma unroll
    for (int i = 0; i < 4; ++i) {
        float4 v = ((const float4*)src)[i];
        float vv[4] = {v.x, v.y, v.z, v.w};
        #pragma unroll
        for (int j = 0; j < 4; ++j) {
            ss += vv[j] * vv[j];
            __nv_bfloat16 h = __float2bfloat16(vv[j]);
            hb[i * 4 + j] = h;
            lb[i * 4 + j] = __float2bfloat16(vv[j] - __bfloat162float(h));
        }
    }
    size_t xo = ((size_t)bt * N_DIM + n) * 64 + q * 16;
    ((uint4*)(g_Xhi + xo))[0] = ((uint4*)hb)[0];
    ((uint4*)(g_Xhi + xo))[1] = ((uint4*)hb)[1];
    ((uint4*)(g_Xlo + xo))[0] = ((uint4*)lb)[0];
    ((uint4*)(g_Xlo + xo))[1] = ((uint4*)lb)[1];
    ss += __shfl_xor_sync(0xffffffffu, ss, 1);
    ss += __shfl_xor_sync(0xffffffffu, ss, 2);
    if (q == 0)
        g_D[(size_t)bt * N_DIM + n] = ss + g_ED[n];
}

// ---------------------------------------------------------------------------
// k_vwt: Vt[bt][c][n] = (W1 @ srcT); c<64 from X, c>=64 from U; bf16 hi/lo out.
// ---------------------------------------------------------------------------
#define VWP 130
__global__ __launch_bounds__(256, 2) void k_vwt(const float* __restrict__ ori,
                                                const float* __restrict__ unc,
                                                const float* __restrict__ W1) {
    extern __shared__ float sm[];
    float (*Ws)[66]  = (float(*)[66])sm;              // (f, c) 64x66
    float (*Bs)[VWP] = (float(*)[VWP])(sm + 64 * 66); // (f, n) 64x130
    const int sx = blockIdx.x, bt = blockIdx.y;
    const int isU = sx >> 2, nc = sx & 3;
    const int n0 = nc * 128;
    const int b = bt / T_DIM, t = bt % T_DIM;
    const int tid = threadIdx.x;
    const float* src = isU ? unc : ori;
    const size_t base = (size_t)b * 786432 + (size_t)t * 64;

    #pragma unroll
    for (int it = 0; it < 4; ++it) {
        int i = tid + it * 256;
        int o = i >> 4, q = i & 15;
        float4 w = *(const float4*)(W1 + o * 64 + q * 4);
        Ws[q * 4 + 0][o] = w.x; Ws[q * 4 + 1][o] = w.y;
        Ws[q * 4 + 2][o] = w.z; Ws[q * 4 + 3][o] = w.w;
    }
    #pragma unroll
    for (int it = 0; it < 8; ++it) {
        int i = tid + it * 256;
        int r = i >> 4, q = i & 15;
        float4 v = *(const float4*)(src + base + (size_t)(n0 + r) * 1536 + q * 4);
        Bs[q * 4 + 0][r] = v.x; Bs[q * 4 + 1][r] = v.y;
        Bs[q * 4 + 2][r] = v.z; Bs[q * 4 + 3][r] = v.w;
    }
    __syncthreads();

    const int ty = tid >> 4, tx = tid & 15;
    u64 acc[4][4] = {};
    #pragma unroll 8
    for (int k = 0; k < 64; ++k) {
        u64 bp[4];
        #pragma unroll
        for (int j = 0; j < 4; ++j) bp[j] = *(const u64*)(&Bs[k][2 * tx + 32 * j]);
        #pragma unroll
        for (int i2 = 0; i2 < 4; ++i2) {
            float a = Ws[k][ty * 4 + i2];
            u64 ad = pack2(a, a);
            #pragma unroll
            for (int j = 0; j < 4; ++j) acc[i2][j] = ffma2(ad, bp[j], acc[i2][j]);
        }
    }
    #pragma unroll
    for (int i2 = 0; i2 < 4; ++i2) {
        size_t row = (size_t)bt * 128 + isU * 64 + ty * 4 + i2;
        #pragma unroll
        for (int j = 0; j < 4; ++j) {
            float2 v = unpack2(acc[i2][j]);
            __nv_bfloat16 hx = __float2bfloat16(v.x), hy = __float2bfloat16(v.y);
            __nv_bfloat162 h2; h2.x = hx; h2.y = hy;
            __nv_bfloat162 l2;
            l2.x = __float2bfloat16(v.x - __bfloat162float(hx));
            l2.y = __float2bfloat16(v.y - __bfloat162float(hy));
            int n = n0 + 2 * tx + 32 * j;
            *(__nv_bfloat162*)(g_Vhi + row * N_DIM + n) = h2;
            *(__nv_bfloat162*)(g_Vlo + row * N_DIM + n) = l2;
        }
    }
}

// ---------------------------------------------------------------------------
// k_fused: per (bt, 128-row block), loop 128-col chunks:
//   GEMM1 (X@X^T chunk, K=64, 3-split) -> +EE(fp32,L2) -> exp(relu-D) ->
//   P(bf16 hi/lo) to smem -> GEMM2 (P @ V chunk, 3-split) accumulating OUT.
// cp.async double-buffered B; V prefetched during GEMM1.
// smem: A 32K | B 2x32K | P 64K | V 64K = 224K.
// ---------------------------------------------------------------------------
#define SA_HI  0
#define SA_LO  16384
#define SB0    32768
#define SB1    65536
#define SP_HI  98304
#define SP_LO  131072
#define SV_HI  163840
#define SV_LO  196608
#define SMEM_FU 229376

__device__ __forceinline__ void load_tile_async(char* dst, const __nv_bfloat16* sp,
                                                int stride, int tid) {
    #pragma unroll
    for (int it = 0; it < 4; ++it) {
        int i = tid + it * 256;
        int row = i >> 3, q = i & 7;
        uint32_t off = (uint32_t)(row * 128 + q * 16);
        off ^= (off >> 3) & 0x70;
        uint32_t d = smem_u32(dst + off);
        asm volatile("cp.async.cg.shared.global [%0], [%1], 16;"
                     :: "r"(d), "l"(__cvta_generic_to_global(sp + (size_t)row * stride + q * 8))
                     : "memory");
    }
}

__global__ __launch_bounds__(256) void k_fused(float* __restrict__ out, size_t uf_off) {
    extern __shared__ char smc[];
    const int rbi = blockIdx.x, bt = blockIdx.y;
    const int rb = rbi * 128;
    const int b = bt / T_DIM, t = bt % T_DIM;
    const int tid = threadIdx.x;
    const int wid = tid >> 5, lane = tid & 31;
    const uint32_t sbase = smem_u32(smc);
    const int wm = (wid & 1) * 64, wn = (wid >> 1) * 32;
    const int mat = lane >> 3, rl = lane & 7;
    const size_t xb = (size_t)bt * N_DIM * 64;

    // Prologue: A tiles (persistent) + B(0)
    load_tile_async(smc + SA_HI, g_Xhi + xb + (size_t)rb * 64, 64, tid);
    load_tile_async(smc + SA_LO, g_Xlo + xb + (size_t)rb * 64, 64, tid);
    load_tile_async(smc + SB0,         g_Xhi + xb, 64, tid);
    load_tile_async(smc + SB0 + 16384, g_Xlo + xb, 64, tid);
    CP_COMMIT();
    cp_wait<0>();
    __syncthreads();

    float accO[4][4][4] = {};
    float rsum[4][2] = {};

    for (int cbi = 0; cbi < 4; ++cbi) {
        const int cb = cbi * 128;
        const uint32_t sB = sbase + ((cbi & 1) ? SB1 : SB0);

        // Prefetch V(c) during GEMM1 (group V)
        const __nv_bfloat16* vh = g_Vhi + (size_t)bt * 128 * N_DIM + cb;
        const __nv_bfloat16* vl = g_Vlo + (size_t)bt * 128 * N_DIM + cb;
        load_tile_async(smc + SV_HI,         vh,      N_DIM, tid);
        load_tile_async(smc + SV_HI + 16384, vh + 64, N_DIM, tid);
        load_tile_async(smc + SV_LO,         vl,      N_DIM, tid);
        load_tile_async(smc + SV_LO + 16384, vl + 64, N_DIM, tid);
        CP_COMMIT();

        // ---- GEMM1: X[rb] @ X[cb]^T, K=64 (4 k16 steps, 3-split) ----
        float accE[4][4][4] = {};
        {
            const uint32_t aH = sbase + SA_HI, aL = sbase + SA_LO;
            const uint32_t bH = sB, bL = sB + 16384;
            #pragma unroll
            for (int kk = 0; kk < 4; ++kk) {
                const int kb = kk * 32;
                uint32_t Bh[4][2], Bl[4][2];
                #pragma unroll
                for (int g = 0; g < 2; ++g) {
                    int nrow = wn + g * 16 + (mat >> 1) * 8 + rl;
                    int col = kb + (mat & 1) * 16;
                    uint32_t th[4], tl[4];
                    ldm4(swadr(bH, nrow, col), th);
                    ldm4(swadr(bL, nrow, col), tl);
                    Bh[2 * g][0] = th[0]; Bh[2 * g][1] = th[1];
                    Bh[2 * g + 1][0] = th[2]; Bh[2 * g + 1][1] = th[3];
                    Bl[2 * g][0] = tl[0]; Bl[2 * g][1] = tl[1];
                    Bl[2 * g + 1][0] = tl[2]; Bl[2 * g + 1][1] = tl[3];
                }
                #pragma unroll
                for (int mi = 0; mi < 4; ++mi) {
                    int row = wm + mi * 16 + (mat & 1) * 8 + rl;
                    int col = kb + (mat >> 1) * 16;
                    uint32_t Ah[4], Al[4];
                    ldm4(swadr(aH, row, col), Ah);
                    ldm4(swadr(aL, row, col), Al);
                    #pragma unroll
                    for (int ni = 0; ni < 4; ++ni) {
                        mma16816(accE[mi][ni], Ah, Bh[ni]);
                        mma16816(accE[mi][ni], Ah, Bl[ni]);
                        mma16816(accE[mi][ni], Al, Bh[ni]);
                    }
                }
            }
        }

        // Prefetch B(c+1) into the other buffer (group B)
        if (cbi < 3) {
            char* nb = smc + ((cbi & 1) ? SB0 : SB1);
            load_tile_async(nb,         g_Xhi + xb + (size_t)(cb + 128) * 64, 64, tid);
            load_tile_async(nb + 16384, g_Xlo + xb + (size_t)(cb + 128) * 64, 64, tid);
            CP_COMMIT();
        }

        // ---- epilogue: +EE (fp32 L2), exp(relu-D), rowsum, pack P ----
        #pragma unroll
        for (int mi = 0; mi < 4; ++mi) {
            #pragma unroll
            for (int h = 0; h < 2; ++h) {
                int rloc = wm + mi * 16 + h * 8 + (lane >> 2);
                int r = rb + rloc;
                float dr = g_D[(size_t)bt * N_DIM + r];
                const float* eerow = g_EE + (size_t)r * N_DIM + cb;
                #pragma unroll
                for (int ni = 0; ni < 4; ++ni) {
                    int n = wn + ni * 8 + (lane & 3) * 2;
                    float2 ee = *(const float2*)(eerow + n);
                    float p0 = __expf(fmaxf(accE[mi][ni][h * 2 + 0] + ee.x, 0.0f) - dr);
                    float p1 = __expf(fmaxf(accE[mi][ni][h * 2 + 1] + ee.y, 0.0f) - dr);
                    rsum[mi][h] += p0 + p1;
                    __nv_bfloat162 hh, ll;
                    hh.x = __float2bfloat16(p0);
                    hh.y = __float2bfloat16(p1);
                    ll.x = __float2bfloat16(p0 - __bfloat162float(hh.x));
                    ll.y = __float2bfloat16(p1 - __bfloat162float(hh.y));
                    int tn = n >> 6, nc2 = n & 63;
                    uint32_t off = (uint32_t)(rloc * 128 + nc2 * 2);
                    off ^= (off >> 3) & 0x70;
                    *(__nv_bfloat162*)(smc + SP_HI + tn * 16384 + off) = hh;
                    *(__nv_bfloat162*)(smc + SP_LO + tn * 16384 + off) = ll;
                }
            }
        }
        // V must be resident (allow B(c+1) still in flight)
        if (cbi < 3) cp_wait<1>(); else cp_wait<0>();
        __syncthreads();

        // ---- GEMM2: OUT += P @ V^T (K = 128 chunk cols, 8 k16 tiles) ----
        #pragma unroll
        for (int kk2 = 0; kk2 < 8; ++kk2) {
            const int tile = kk2 >> 2, kb = (kk2 & 3) * 32;
            const uint32_t aH = sbase + SP_HI + tile * 16384;
            const uint32_t aL = sbase + SP_LO + tile * 16384;
            const uint32_t bH = sbase + SV_HI + tile * 16384;
            const uint32_t bL = sbase + SV_LO + tile * 16384;
            uint32_t Bh[4][2], Bl[4][2];
            #pragma unroll
            for (int g = 0; g < 2; ++g) {
                int nrow = wn + g * 16 + (mat >> 1) * 8 + rl;
                int col = kb + (mat & 1) * 16;
                uint32_t th[4], tl[4];
                ldm4(swadr(bH, nrow, col), th);
                ldm4(swadr(bL, nrow, col), tl);
                Bh[2 * g][0] = th[0]; Bh[2 * g][1] = th[1];
                Bh[2 * g + 1][0] = th[2]; Bh[2 * g + 1][1] = th[3];
                Bl[2 * g][0] = tl[0]; Bl[2 * g][1] = tl[1];
                Bl[2 * g + 1][0] = tl[2]; Bl[2 * g + 1][1] = tl[3];
            }
            #pragma unroll
            for (int mi = 0; mi < 4; ++mi) {
                int row = wm + mi * 16 + (mat & 1) * 8 + rl;
                int col = kb + (mat >> 1) * 16;
                uint32_t Ah[4], Al[4];
                ldm4(swadr(aH, row, col), Ah);
                ldm4(swadr(aL, row, col), Al);
                #pragma unroll
                for (int ni = 0; ni < 4; ++ni) {
                    mma16816(accO[mi][ni], Ah, Bh[ni]);
                    mma16816(accO[mi][ni], Ah, Bl[ni]);
                    mma16816(accO[mi][ni], Al, Bh[ni]);
                }
            }
        }
        cp_wait<0>();
        __syncthreads();
    }

    // ---- rowsum cross-warp reduce (reuse B buffers) ----
    float* rs = (float*)(smc + SB0);  // [4 wn-groups][128 rows]
    #pragma unroll
    for (int mi = 0; mi < 4; ++mi) {
        #pragma unroll
        for (int h = 0; h < 2; ++h) {
            float v = rsum[mi][h];
            v += __shfl_xor_sync(0xffffffffu, v, 1);
            v += __shfl_xor_sync(0xffffffffu, v, 2);
            if ((lane & 3) == 0) {
                int rloc = wm + mi * 16 + h * 8 + (lane >> 2);
                rs[(wid >> 1) * 128 + rloc] = v;
            }
        }
    }
    __syncthreads();

    // ---- final: normalize, relu, scatter ----
    #pragma unroll
    for (int mi = 0; mi < 4; ++mi) {
        #pragma unroll
        for (int h = 0; h < 2; ++h) {
            int rloc = wm + mi * 16 + h * 8 + (lane >> 2);
            int n = rb + rloc;
            float tot = rs[rloc] + rs[128 + rloc] + rs[256 + rloc] + rs[384 + rloc];
            float inv = 1.0f / tot;
            size_t obase = (size_t)b * 786432 + (size_t)n * 1536 + (size_t)t * 64;
            #pragma unroll
            for (int ni = 0; ni < 4; ++ni) {
                int ch = wn + ni * 8 + (lane & 3) * 2;
                float2 v;
                v.x = fmaxf(accO[mi][ni][h * 2 + 0] * inv, 0.0f);
                v.y = fmaxf(accO[mi][ni][h * 2 + 1] * inv, 0.0f);
                if (ch < 64) *(float2*)(out + obase + ch) = v;
                else         *(float2*)(out + uf_off + obase + (ch - 64)) = v;
            }
        }
    }
}

// ---------------------------------------------------------------------------
extern "C" void kernel_launch(void* const* d_in, const int* in_sizes, int n_in,
                              void* d_out, int out_size) {
    const float* ori = (const float*)d_in[0];   // (16,512,24,64)
    const float* unc = (const float*)d_in[1];   // (16,512,24,64)
    const float* emb = (const float*)d_in[2];   // (512,64)
    const float* W1  = (const float*)d_in[3];   // (64,64)
    float* out = (float*)d_out;                 // [of | uf]
    const size_t uf_off = (size_t)out_size / 2;

    const int SMEM_VWT = (64 * 66 + 64 * VWP) * 4;  // 50176 B
    cudaFuncSetAttribute(k_vwt, cudaFuncAttributeMaxDynamicSharedMemorySize, SMEM_VWT);
    cudaFuncSetAttribute(k_fused, cudaFuncAttributeMaxDynamicSharedMemorySize, SMEM_FU);

    k_ee<<<dim3(8, 8), 256>>>(emb);
    k_prep<<<dim3(8, BT_DIM), 256>>>(ori);
    k_vwt<<<dim3(8, BT_DIM), 256, SMEM_VWT>>>(ori, unc, W1);
    k_fused<<<dim3(4, BT_DIM), 256, SMEM_FU>>>(out, uf_off);
}

// round 15
// speedup vs baseline: 2.6424x; 1.1055x over previous
#include <cuda_runtime.h>
#include <cuda_bf16.h>
#include <cstddef>
#include <cstdint>

// B=16, N=512, T=24, F=64, BT=384
#define T_DIM 24
#define N_DIM 512
#define BT_DIM 384

// Scratch (device globals: allocation-free per harness rules)
static __device__ float g_EE[N_DIM * N_DIM];                                 // 1 MB, emb@emb^T
static __device__ float g_ED[N_DIM];                                         // ||emb_n||^2
static __device__ float g_D[(size_t)BT_DIM * N_DIM];                         // diag shift
static __device__ __nv_bfloat16 g_Xhi[(size_t)BT_DIM * N_DIM * 64];          // 25 MB
static __device__ __nv_bfloat16 g_Xlo[(size_t)BT_DIM * N_DIM * 64];          // 25 MB
static __device__ __nv_bfloat16 g_Vhi[(size_t)BT_DIM * 128 * N_DIM];         // 50 MB
static __device__ __nv_bfloat16 g_Vlo[(size_t)BT_DIM * 128 * N_DIM];         // 50 MB

typedef unsigned long long u64;
__device__ __forceinline__ u64 pack2(float lo, float hi) {
    u64 r; asm("mov.b64 %0, {%1, %2};" : "=l"(r) : "f"(lo), "f"(hi)); return r;
}
__device__ __forceinline__ u64 ffma2(u64 a, u64 b, u64 c) {
    u64 d; asm("fma.rn.f32x2 %0, %1, %2, %3;" : "=l"(d) : "l"(a), "l"(b), "l"(c)); return d;
}
__device__ __forceinline__ float2 unpack2(u64 v) {
    float2 r; asm("mov.b64 {%0, %1}, %2;" : "=f"(r.x), "=f"(r.y) : "l"(v)); return r;
}

// ---- warp-level tensor core plumbing (sm_80 baseline PTX) ------------------
__device__ __forceinline__ uint32_t smem_u32(const void* p) {
    uint32_t a;
    asm("{ .reg .u64 t; cvta.to.shared.u64 t, %1; cvt.u32.u64 %0, t; }" : "=r"(a) : "l"(p));
    return a;
}
__device__ __forceinline__ void ldm4(uint32_t addr, uint32_t* r) {
    asm volatile("ldmatrix.sync.aligned.m8n8.x4.shared.b16 {%0,%1,%2,%3}, [%4];"
                 : "=r"(r[0]), "=r"(r[1]), "=r"(r[2]), "=r"(r[3]) : "r"(addr));
}
__device__ __forceinline__ void mma16816(float* d, const uint32_t* a, const uint32_t* b) {
    asm volatile("mma.sync.aligned.m16n8k16.row.col.f32.bf16.bf16.f32 "
        "{%0,%1,%2,%3}, {%4,%5,%6,%7}, {%8,%9}, {%0,%1,%2,%3};"
        : "+f"(d[0]), "+f"(d[1]), "+f"(d[2]), "+f"(d[3])
        : "r"(a[0]), "r"(a[1]), "r"(a[2]), "r"(a[3]), "r"(b[0]), "r"(b[1]));
}
// SW128 swizzle for 128B-pitch tiles
__device__ __forceinline__ uint32_t swadr(uint32_t base, int row, int colb) {
    uint32_t off = row * 128 + colb;
    return base + (off ^ ((off >> 3) & 0x70));
}
#define CP_COMMIT() asm volatile("cp.async.commit_group;" ::: "memory")
template <int N>
__device__ __forceinline__ void cp_wait() {
    asm volatile("cp.async.wait_group %0;" :: "n"(N) : "memory");
}

// ---------------------------------------------------------------------------
// k_ee: EE = emb @ emb^T (512x512, K=64) in fp32; diag -> g_ED.
// ---------------------------------------------------------------------------
__global__ void k_ee(const float* __restrict__ emb) {
    __shared__ float As[64][68];
    __shared__ float Bs[64][65];
    const int rb = blockIdx.y * 64, cb = blockIdx.x * 64;
    const int tid = threadIdx.x;
    #pragma unroll
    for (int it = 0; it < 4; ++it) {
        int i = tid + it * 256;
        int r = i >> 4, k4 = i & 15;
        float4 a = *(const float4*)(emb + (rb + r) * 64 + k4 * 4);
        *(float4*)(&As[r][k4 * 4]) = a;
        float4 w = *(const float4*)(emb + (cb + r) * 64 + k4 * 4);
        Bs[k4 * 4 + 0][r] = w.x; Bs[k4 * 4 + 1][r] = w.y;
        Bs[k4 * 4 + 2][r] = w.z; Bs[k4 * 4 + 3][r] = w.w;
    }
    __syncthreads();
    const int ty = tid >> 4, tx = tid & 15;
    float acc[4][4] = {};
    #pragma unroll 8
    for (int k = 0; k < 64; ++k) {
        float a[4], b[4];
        #pragma unroll
        for (int i = 0; i < 4; ++i) a[i] = As[ty * 4 + i][k];
        #pragma unroll
        for (int j = 0; j < 4; ++j) b[j] = Bs[k][tx + 16 * j];
        #pragma unroll
        for (int i = 0; i < 4; ++i)
            #pragma unroll
            for (int j = 0; j < 4; ++j) acc[i][j] = fmaf(a[i], b[j], acc[i][j]);
    }
    #pragma unroll
    for (int i = 0; i < 4; ++i)
        #pragma unroll
        for (int j = 0; j < 4; ++j) {
            int r = rb + ty * 4 + i, c = cb + tx + 16 * j;
            g_EE[r * N_DIM + c] = acc[i][j];
            if (r == c) g_ED[r] = acc[i][j];
        }
}

// ---------------------------------------------------------------------------
// k_prep: X -> bf16 hi/lo (per-bt layout), D[bt][n] = ||x||^2 + ||emb_n||^2
// ---------------------------------------------------------------------------
__global__ void k_prep(const float* __restrict__ ori) {
    const int bt = blockIdx.y, b = bt / T_DIM, t = bt % T_DIM;
    const int tid = threadIdx.x;
    const int rl = tid >> 2, q = tid & 3;
    const int n = blockIdx.x * 64 + rl;
    const float* src = ori + (size_t)b * 786432 + (size_t)n * 1536 + (size_t)t * 64 + q * 16;
    float ss = 0.0f;
    __align__(16) __nv_bfloat16 hb[16], lb[16];
    #pragma unroll
    for (int i = 0; i < 4; ++i) {
        float4 v = ((const float4*)src)[i];
        float vv[4] = {v.x, v.y, v.z, v.w};
        #pragma unroll
        for (int j = 0; j < 4; ++j) {
            ss += vv[j] * vv[j];
            __nv_bfloat16 h = __float2bfloat16(vv[j]);
            hb[i * 4 + j] = h;
            lb[i * 4 + j] = __float2bfloat16(vv[j] - __bfloat162float(h));
        }
    }
    size_t xo = ((size_t)bt * N_DIM + n) * 64 + q * 16;
    ((uint4*)(g_Xhi + xo))[0] = ((uint4*)hb)[0];
    ((uint4*)(g_Xhi + xo))[1] = ((uint4*)hb)[1];
    ((uint4*)(g_Xlo + xo))[0] = ((uint4*)lb)[0];
    ((uint4*)(g_Xlo + xo))[1] = ((uint4*)lb)[1];
    ss += __shfl_xor_sync(0xffffffffu, ss, 1);
    ss += __shfl_xor_sync(0xffffffffu, ss, 2);
    if (q == 0)
        g_D[(size_t)bt * N_DIM + n] = ss + g_ED[n];
}

// ---------------------------------------------------------------------------
// k_vwt: Vt[bt][c][n] = (W1 @ srcT); c<64 from X, c>=64 from U; bf16 hi/lo out.
// ---------------------------------------------------------------------------
#define VWP 130
__global__ __launch_bounds__(256, 2) void k_vwt(const float* __restrict__ ori,
                                                const float* __restrict__ unc,
                                                const float* __restrict__ W1) {
    extern __shared__ float sm[];
    float (*Ws)[66]  = (float(*)[66])sm;              // (f, c) 64x66
    float (*Bs)[VWP] = (float(*)[VWP])(sm + 64 * 66); // (f, n) 64x130
    const int sx = blockIdx.x, bt = blockIdx.y;
    const int isU = sx >> 2, nc = sx & 3;
    const int n0 = nc * 128;
    const int b = bt / T_DIM, t = bt % T_DIM;
    const int tid = threadIdx.x;
    const float* src = isU ? unc : ori;
    const size_t base = (size_t)b * 786432 + (size_t)t * 64;

    #pragma unroll
    for (int it = 0; it < 4; ++it) {
        int i = tid + it * 256;
        int o = i >> 4, q = i & 15;
        float4 w = *(const float4*)(W1 + o * 64 + q * 4);
        Ws[q * 4 + 0][o] = w.x; Ws[q * 4 + 1][o] = w.y;
        Ws[q * 4 + 2][o] = w.z; Ws[q * 4 + 3][o] = w.w;
    }
    #pragma unroll
    for (int it = 0; it < 8; ++it) {
        int i = tid + it * 256;
        int r = i >> 4, q = i & 15;
        float4 v = *(const float4*)(src + base + (size_t)(n0 + r) * 1536 + q * 4);
        Bs[q * 4 + 0][r] = v.x; Bs[q * 4 + 1][r] = v.y;
        Bs[q * 4 + 2][r] = v.z; Bs[q * 4 + 3][r] = v.w;
    }
    __syncthreads();

    const int ty = tid >> 4, tx = tid & 15;
    u64 acc[4][4] = {};
    #pragma unroll 8
    for (int k = 0; k < 64; ++k) {
        u64 bp[4];
        #pragma unroll
        for (int j = 0; j < 4; ++j) bp[j] = *(const u64*)(&Bs[k][2 * tx + 32 * j]);
        #pragma unroll
        for (int i2 = 0; i2 < 4; ++i2) {
            float a = Ws[k][ty * 4 + i2];
            u64 ad = pack2(a, a);
            #pragma unroll
            for (int j = 0; j < 4; ++j) acc[i2][j] = ffma2(ad, bp[j], acc[i2][j]);
        }
    }
    #pragma unroll
    for (int i2 = 0; i2 < 4; ++i2) {
        size_t row = (size_t)bt * 128 + isU * 64 + ty * 4 + i2;
        #pragma unroll
        for (int j = 0; j < 4; ++j) {
            float2 v = unpack2(acc[i2][j]);
            __nv_bfloat16 hx = __float2bfloat16(v.x), hy = __float2bfloat16(v.y);
            __nv_bfloat162 h2; h2.x = hx; h2.y = hy;
            __nv_bfloat162 l2;
            l2.x = __float2bfloat16(v.x - __bfloat162float(hx));
            l2.y = __float2bfloat16(v.y - __bfloat162float(hy));
            int n = n0 + 2 * tx + 32 * j;
            *(__nv_bfloat162*)(g_Vhi + row * N_DIM + n) = h2;
            *(__nv_bfloat162*)(g_Vlo + row * N_DIM + n) = l2;
        }
    }
}

// ---------------------------------------------------------------------------
// k_fused: 64-row CTA tile, 8 chunks of 64 cols; 2 CTAs/SM (96KB smem, <=128 regs)
//   GEMM1 (X@X^T chunk, K=64, 3-split) -> +EE(fp32,L2) -> exp(relu-D) ->
//   P(bf16 hi/lo) to smem -> GEMM2 (P @ V chunk, 3-split) accumulating OUT.
// cp.async: double-buffered B, V prefetched during GEMM1.
// smem: A 16K | B 2x16K | P 16K | V 32K = 96K.
// ---------------------------------------------------------------------------
#define SA_HI  0
#define SA_LO  8192
#define SB0    16384
#define SB1    32768
#define SP_HI  49152
#define SP_LO  57344
#define SV     65536
#define SMEM_FU 98304

__device__ __forceinline__ void load_tile64_async(char* dst, const __nv_bfloat16* sp,
                                                  int stride, int tid) {
    #pragma unroll
    for (int it = 0; it < 2; ++it) {
        int i = tid + it * 256;
        int row = i >> 3, q = i & 7;
        uint32_t off = (uint32_t)(row * 128 + q * 16);
        off ^= (off >> 3) & 0x70;
        uint32_t d = smem_u32(dst + off);
        asm volatile("cp.async.cg.shared.global [%0], [%1], 16;"
                     :: "r"(d), "l"(__cvta_generic_to_global(sp + (size_t)row * stride + q * 8))
                     : "memory");
    }
}

__global__ __launch_bounds__(256, 2) void k_fused(float* __restrict__ out, size_t uf_off) {
    extern __shared__ char smc[];
    const int rbi = blockIdx.x, bt = blockIdx.y;
    const int rb = rbi * 64;
    const int b = bt / T_DIM, t = bt % T_DIM;
    const int tid = threadIdx.x;
    const int wid = tid >> 5, lane = tid & 31;
    const uint32_t sbase = smem_u32(smc);
    const int wmr = (wid & 1) * 32;          // row group (both GEMMs)
    const int wn1 = (wid >> 1) * 16;         // GEMM1 col group (16 cols)
    const int wn2 = (wid >> 1) * 32;         // GEMM2 ch group (32 ch)
    const int mat = lane >> 3, rl = lane & 7;
    const size_t xb = (size_t)bt * N_DIM * 64;

    // Prologue: A tiles (persistent) + B(0)
    load_tile64_async(smc + SA_HI, g_Xhi + xb + (size_t)rb * 64, 64, tid);
    load_tile64_async(smc + SA_LO, g_Xlo + xb + (size_t)rb * 64, 64, tid);
    load_tile64_async(smc + SB0,        g_Xhi + xb, 64, tid);
    load_tile64_async(smc + SB0 + 8192, g_Xlo + xb, 64, tid);
    CP_COMMIT();
    cp_wait<0>();
    __syncthreads();

    float accO[2][4][4] = {};
    float rsum[2][2] = {};

    for (int cbi = 0; cbi < 8; ++cbi) {
        const int cb = cbi * 64;
        const uint32_t sB = sbase + ((cbi & 1) ? SB1 : SB0);

        // Prefetch V chunk (128 ch x 64 K-cols, hi/lo as 2 tiles each)
        const __nv_bfloat16* vh = g_Vhi + (size_t)bt * 128 * N_DIM + cb;
        const __nv_bfloat16* vl = g_Vlo + (size_t)bt * 128 * N_DIM + cb;
        load_tile64_async(smc + SV,          vh,                     N_DIM, tid);
        load_tile64_async(smc + SV + 8192,   vh + (size_t)64 * N_DIM, N_DIM, tid);
        load_tile64_async(smc + SV + 16384,  vl,                     N_DIM, tid);
        load_tile64_async(smc + SV + 24576,  vl + (size_t)64 * N_DIM, N_DIM, tid);
        CP_COMMIT();

        // ---- GEMM1: X[rb:+64] @ X[cb:+64]^T, K=64 (4 k16, 3-split) ----
        float accE[2][2][4] = {};
        {
            const uint32_t aH = sbase + SA_HI, aL = sbase + SA_LO;
            const uint32_t bH = sB, bL = sB + 8192;
            #pragma unroll
            for (int kk = 0; kk < 4; ++kk) {
                const int kb = kk * 32;
                uint32_t Bh[2][2], Bl[2][2];
                {
                    int nrow = wn1 + (mat >> 1) * 8 + rl;
                    int col = kb + (mat & 1) * 16;
                    uint32_t th[4], tl[4];
                    ldm4(swadr(bH, nrow, col), th);
                    ldm4(swadr(bL, nrow, col), tl);
                    Bh[0][0] = th[0]; Bh[0][1] = th[1];
                    Bh[1][0] = th[2]; Bh[1][1] = th[3];
                    Bl[0][0] = tl[0]; Bl[0][1] = tl[1];
                    Bl[1][0] = tl[2]; Bl[1][1] = tl[3];
                }
                #pragma unroll
                for (int mi = 0; mi < 2; ++mi) {
                    int row = wmr + mi * 16 + (mat & 1) * 8 + rl;
                    int col = kb + (mat >> 1) * 16;
                    uint32_t Ah[4], Al[4];
                    ldm4(swadr(aH, row, col), Ah);
                    ldm4(swadr(aL, row, col), Al);
                    #pragma unroll
                    for (int ni = 0; ni < 2; ++ni) {
                        mma16816(accE[mi][ni], Ah, Bh[ni]);
                        mma16816(accE[mi][ni], Ah, Bl[ni]);
                        mma16816(accE[mi][ni], Al, Bh[ni]);
                    }
                }
            }
        }

        // Prefetch B(c+1)
        if (cbi < 7) {
            char* nb = smc + ((cbi & 1) ? SB0 : SB1);
            load_tile64_async(nb,        g_Xhi + xb + (size_t)(cb + 64) * 64, 64, tid);
            load_tile64_async(nb + 8192, g_Xlo + xb + (size_t)(cb + 64) * 64, 64, tid);
            CP_COMMIT();
        }

        // ---- epilogue: +EE (fp32 L2), exp(relu-D), rowsum, pack P ----
        #pragma unroll
        for (int mi = 0; mi < 2; ++mi) {
            #pragma unroll
            for (int h = 0; h < 2; ++h) {
                int rloc = wmr + mi * 16 + h * 8 + (lane >> 2);
                int r = rb + rloc;
                float dr = g_D[(size_t)bt * N_DIM + r];
                const float* eerow = g_EE + (size_t)r * N_DIM + cb;
                #pragma unroll
                for (int ni = 0; ni < 2; ++ni) {
                    int n = wn1 + ni * 8 + (lane & 3) * 2;
                    float2 ee = *(const float2*)(eerow + n);
                    float p0 = __expf(fmaxf(accE[mi][ni][h * 2 + 0] + ee.x, 0.0f) - dr);
                    float p1 = __expf(fmaxf(accE[mi][ni][h * 2 + 1] + ee.y, 0.0f) - dr);
                    rsum[mi][h] += p0 + p1;
                    __nv_bfloat162 hh, ll;
                    hh.x = __float2bfloat16(p0);
                    hh.y = __float2bfloat16(p1);
                    ll.x = __float2bfloat16(p0 - __bfloat162float(hh.x));
                    ll.y = __float2bfloat16(p1 - __bfloat162float(hh.y));
                    uint32_t off = (uint32_t)(rloc * 128 + n * 2);
                    off ^= (off >> 3) & 0x70;
                    *(__nv_bfloat162*)(smc + SP_HI + off) = hh;
                    *(__nv_bfloat162*)(smc + SP_LO + off) = ll;
                }
            }
        }
        // V must be resident (allow B(c+1) still in flight)
        if (cbi < 7) cp_wait<1>(); else cp_wait<0>();
        __syncthreads();

        // ---- GEMM2: OUT += P @ V^T (K = 64 chunk cols, 4 k16) ----
        {
            const uint32_t aH = sbase + SP_HI, aL = sbase + SP_LO;
            #pragma unroll
            for (int kk = 0; kk < 4; ++kk) {
                const int kb = kk * 32;
                uint32_t Bh[4][2], Bl[4][2];
                #pragma unroll
                for (int g = 0; g < 2; ++g) {
                    int grp = wn2 + g * 16;
                    int tile = grp >> 6;
                    int nr = (grp & 63) + (mat >> 1) * 8 + rl;
                    int col = kb + (mat & 1) * 16;
                    uint32_t bHt = sbase + SV + tile * 8192;
                    uint32_t bLt = sbase + SV + 16384 + tile * 8192;
                    uint32_t th[4], tl[4];
                    ldm4(swadr(bHt, nr, col), th);
                    ldm4(swadr(bLt, nr, col), tl);
                    Bh[2 * g][0] = th[0]; Bh[2 * g][1] = th[1];
                    Bh[2 * g + 1][0] = th[2]; Bh[2 * g + 1][1] = th[3];
                    Bl[2 * g][0] = tl[0]; Bl[2 * g][1] = tl[1];
                    Bl[2 * g + 1][0] = tl[2]; Bl[2 * g + 1][1] = tl[3];
                }
                #pragma unroll
                for (int mi = 0; mi < 2; ++mi) {
                    int row = wmr + mi * 16 + (mat & 1) * 8 + rl;
                    int col = kb + (mat >> 1) * 16;
                    uint32_t Ah[4], Al[4];
                    ldm4(swadr(aH, row, col), Ah);
                    ldm4(swadr(aL, row, col), Al);
                    #pragma unroll
                    for (int ni = 0; ni < 4; ++ni) {
                        mma16816(accO[mi][ni], Ah, Bh[ni]);
                        mma16816(accO[mi][ni], Ah, Bl[ni]);
                        mma16816(accO[mi][ni], Al, Bh[ni]);
                    }
                }
            }
        }
        cp_wait<0>();
        __syncthreads();
    }

    // ---- rowsum cross-warp reduce (reuse B buffers) ----
    float* rs = (float*)(smc + SB0);  // [4 n-groups][64 rows]
    #pragma unroll
    for (int mi = 0; mi < 2; ++mi) {
        #pragma unroll
        for (int h = 0; h < 2; ++h) {
            float v = rsum[mi][h];
            v += __shfl_xor_sync(0xffffffffu, v, 1);
            v += __shfl_xor_sync(0xffffffffu, v, 2);
            if ((lane & 3) == 0) {
                int rloc = wmr + mi * 16 + h * 8 + (lane >> 2);
                rs[(wid >> 1) * 64 + rloc] = v;
            }
        }
    }
    __syncthreads();

    // ---- final: normalize, relu, scatter ----
    #pragma unroll
    for (int mi = 0; mi < 2; ++mi) {
        #pragma unroll
        for (int h = 0; h < 2; ++h) {
            int rloc = wmr + mi * 16 + h * 8 + (lane >> 2);
            int n = rb + rloc;
            float tot = rs[rloc] + rs[64 + rloc] + rs[128 + rloc] + rs[192 + rloc];
            float inv = 1.0f / tot;
            size_t obase = (size_t)b * 786432 + (size_t)n * 1536 + (size_t)t * 64;
            #pragma unroll
            for (int ni = 0; ni < 4; ++ni) {
                int ch = wn2 + ni * 8 + (lane & 3) * 2;
                float2 v;
                v.x = fmaxf(accO[mi][ni][h * 2 + 0] * inv, 0.0f);
                v.y = fmaxf(accO[mi][ni][h * 2 + 1] * inv, 0.0f);
                if (ch < 64) *(float2*)(out + obase + ch) = v;
                else         *(float2*)(out + uf_off + obase + (ch - 64)) = v;
            }
        }
    }
}

// ---------------------------------------------------------------------------
extern "C" void kernel_launch(void* const* d_in, const int* in_sizes, int n_in,
                              void* d_out, int out_size) {
    const float* ori = (const float*)d_in[0];   // (16,512,24,64)
    const float* unc = (const float*)d_in[1];   // (16,512,24,64)
    const float* emb = (const float*)d_in[2];   // (512,64)
    const float* W1  = (const float*)d_in[3];   // (64,64)
    float* out = (float*)d_out;                 // [of | uf]
    const size_t uf_off = (size_t)out_size / 2;

    const int SMEM_VWT = (64 * 66 + 64 * VWP) * 4;  // 50176 B
    cudaFuncSetAttribute(k_vwt, cudaFuncAttributeMaxDynamicSharedMemorySize, SMEM_VWT);
    cudaFuncSetAttribute(k_fused, cudaFuncAttributeMaxDynamicSharedMemorySize, SMEM_FU);

    k_ee<<<dim3(8, 8), 256>>>(emb);
    k_prep<<<dim3(8, BT_DIM), 256>>>(ori);
    k_vwt<<<dim3(8, BT_DIM), 256, SMEM_VWT>>>(ori, unc, W1);
    k_fused<<<dim3(8, BT_DIM), 256, SMEM_FU>>>(out, uf_off);
}